// round 1
// baseline (speedup 1.0000x reference)
#include <cuda_runtime.h>
#include <math.h>

// Problem constants
constexpr int Bc   = 2;
constexpr int Tc   = 2048;
constexpr int Ec   = 1024;
constexpr int Hc   = 16;
constexpr int Dc   = 64;
constexpr int BHc  = Bc * Hc;      // 32
constexpr int Mtok = Bc * Tc;      // 4096
constexpr float LAMBDA_INIT = 0.4707130183435843f;  // 0.8 - 0.6*exp(-0.6)
constexpr float EPSc = 1e-5f;

// Scratch (device globals: allocation-free rule)
__device__ float g_q1[BHc * Tc * Dc];
__device__ float g_k1[BHc * Tc * Dc];
__device__ float g_q2[BHc * Tc * Dc];
__device__ float g_k2[BHc * Tc * Dc];
__device__ float g_v [BHc * Tc * Dc];
__device__ float g_s1[(size_t)BHc * Tc * Tc];   // 512 MB
__device__ float g_s2[(size_t)BHc * Tc * Tc];   // 512 MB
__device__ float g_attn[(size_t)Mtok * Ec];
__device__ float g_lambda;

// -------------------------------------------------------------------------
// lambda = exp(sum(lq1*lk1)) - exp(sum(lq2*lk2)) + LAMBDA_INIT
// -------------------------------------------------------------------------
__global__ void lambda_kernel(const float* __restrict__ lq1, const float* __restrict__ lk1,
                              const float* __restrict__ lq2, const float* __restrict__ lk2)
{
    __shared__ float s1[64], s2[64];
    int t = threadIdx.x;
    s1[t] = lq1[t] * lk1[t];
    s2[t] = lq2[t] * lk2[t];
    __syncthreads();
    if (t == 0) {
        float a = 0.f, b = 0.f;
        #pragma unroll
        for (int i = 0; i < 64; i++) { a += s1[i]; b += s2[i]; }
        g_lambda = expf(a) - expf(b) + LAMBDA_INIT;
    }
}

// -------------------------------------------------------------------------
// Generic NT SGEMM: C[m,n] = scale * sum_k A[m,k] * Bw[n,k]
//   A: row-major [M,K] (lda=K), Bw: row-major [N,K] (ldb=K)
//   Tiles: 128x128x16, 256 threads, 8x8 microtile.
//   out_mode 0: C row-major [M,N]  (N = gridDim.x*128)
//   out_mode 1: head-split projection layout [B,H,T,D] (m=b*T+t, n=h*D+d)
//   Batched via blockIdx.z with element strides sA/sB/sC.
// Requires M%128==0, N%128==0, K%16==0 (true for all uses here).
// -------------------------------------------------------------------------
__global__ __launch_bounds__(256) void sgemm_nt(
    const float* __restrict__ A, const float* __restrict__ Bw,
    float* __restrict__ C, int K,
    long long sA, long long sB, long long sC,
    float scale, int out_mode)
{
    __shared__ float As[16][132];
    __shared__ float Bs[16][132];

    const int bz = blockIdx.z;
    A  += (long long)bz * sA;
    Bw += (long long)bz * sB;
    C  += (long long)bz * sC;

    const int m0 = blockIdx.y * 128;
    const int n0 = blockIdx.x * 128;
    const int N  = gridDim.x * 128;
    const int tid = threadIdx.x;
    const int tx = tid & 15, ty = tid >> 4;

    float acc[8][8];
    #pragma unroll
    for (int i = 0; i < 8; i++)
        #pragma unroll
        for (int j = 0; j < 8; j++) acc[i][j] = 0.f;

    for (int k0 = 0; k0 < K; k0 += 16) {
        #pragma unroll
        for (int l = 0; l < 2; l++) {
            int idx = tid + l * 256;          // 0..511
            int r   = idx >> 2;               // tile row 0..127
            int c4  = (idx & 3) << 2;         // k sub-offset 0,4,8,12
            float4 va = *(const float4*)(A + (long long)(m0 + r) * K + k0 + c4);
            As[c4+0][r] = va.x; As[c4+1][r] = va.y; As[c4+2][r] = va.z; As[c4+3][r] = va.w;
            float4 vb = *(const float4*)(Bw + (long long)(n0 + r) * K + k0 + c4);
            Bs[c4+0][r] = vb.x; Bs[c4+1][r] = vb.y; Bs[c4+2][r] = vb.z; Bs[c4+3][r] = vb.w;
        }
        __syncthreads();

        #pragma unroll
        for (int kk = 0; kk < 16; kk++) {
            float ra[8], rb[8];
            #pragma unroll
            for (int i = 0; i < 8; i++) ra[i] = As[kk][ty * 8 + i];
            #pragma unroll
            for (int j = 0; j < 8; j++) rb[j] = Bs[kk][tx * 8 + j];
            #pragma unroll
            for (int i = 0; i < 8; i++)
                #pragma unroll
                for (int j = 0; j < 8; j++) acc[i][j] += ra[i] * rb[j];
        }
        __syncthreads();
    }

    if (out_mode == 0) {
        #pragma unroll
        for (int i = 0; i < 8; i++) {
            int m = m0 + ty * 8 + i;
            #pragma unroll
            for (int j = 0; j < 8; j += 4) {
                float4 v4;
                v4.x = acc[i][j+0] * scale;
                v4.y = acc[i][j+1] * scale;
                v4.z = acc[i][j+2] * scale;
                v4.w = acc[i][j+3] * scale;
                *(float4*)(C + (long long)m * N + n0 + tx * 8 + j) = v4;
            }
        }
    } else {
        // projection layout: m = b*T + t ; n = h*D + d -> ((b*H+h)*T + t)*D + d
        #pragma unroll
        for (int i = 0; i < 8; i++) {
            int m  = m0 + ty * 8 + i;
            int bb = m >> 11;                  // / Tc
            int t  = m & (Tc - 1);
            #pragma unroll
            for (int j = 0; j < 8; j++) {
                int n = n0 + tx * 8 + j;
                int h = n >> 6;                // / Dc
                int d = n & (Dc - 1);
                C[((long long)(bb * Hc + h) * Tc + t) * Dc + d] = acc[i][j] * scale;
            }
        }
    }
}

// -------------------------------------------------------------------------
// Row softmax in place. One block per row of length T=2048. 256 threads.
// -------------------------------------------------------------------------
__global__ __launch_bounds__(256) void softmax_rows(float* __restrict__ S)
{
    __shared__ float red[8];
    float* p = S + (size_t)blockIdx.x * Tc;
    const int tid  = threadIdx.x;
    const int lane = tid & 31;
    const int wrp  = tid >> 5;

    float4 v0 = ((const float4*)p)[tid];
    float4 v1 = ((const float4*)p)[tid + 256];

    float m = fmaxf(fmaxf(fmaxf(v0.x, v0.y), fmaxf(v0.z, v0.w)),
                    fmaxf(fmaxf(v1.x, v1.y), fmaxf(v1.z, v1.w)));
    #pragma unroll
    for (int o = 16; o; o >>= 1) m = fmaxf(m, __shfl_xor_sync(0xffffffffu, m, o));
    if (lane == 0) red[wrp] = m;
    __syncthreads();
    m = red[0];
    #pragma unroll
    for (int i = 1; i < 8; i++) m = fmaxf(m, red[i]);
    __syncthreads();

    v0.x = expf(v0.x - m); v0.y = expf(v0.y - m);
    v0.z = expf(v0.z - m); v0.w = expf(v0.w - m);
    v1.x = expf(v1.x - m); v1.y = expf(v1.y - m);
    v1.z = expf(v1.z - m); v1.w = expf(v1.w - m);

    float s = v0.x + v0.y + v0.z + v0.w + v1.x + v1.y + v1.z + v1.w;
    #pragma unroll
    for (int o = 16; o; o >>= 1) s += __shfl_xor_sync(0xffffffffu, s, o);
    if (lane == 0) red[wrp] = s;
    __syncthreads();
    s = red[0];
    #pragma unroll
    for (int i = 1; i < 8; i++) s += red[i];

    float inv = 1.0f / s;
    v0.x *= inv; v0.y *= inv; v0.z *= inv; v0.w *= inv;
    v1.x *= inv; v1.y *= inv; v1.z *= inv; v1.w *= inv;
    ((float4*)p)[tid]       = v0;
    ((float4*)p)[tid + 256] = v1;
}

// -------------------------------------------------------------------------
// PV GEMM: Out[bh, m, d] = sum_k (P1[m,k] - lam*P2[m,k]) * V[bh, k, d]
//   P1/P2: [T,T] row-major per batch, V: [T,D] row-major per batch.
//   Tiles: 128x64(=full D)x16, 256 threads, 8x4 microtile.
// -------------------------------------------------------------------------
__global__ __launch_bounds__(256) void gemm_pv(
    const float* __restrict__ P1, const float* __restrict__ P2,
    const float* __restrict__ V, float* __restrict__ Out)
{
    __shared__ float Ps[16][132];
    __shared__ float Vs[16][68];

    const int bh = blockIdx.z;
    const float* p1 = P1 + (size_t)bh * Tc * Tc;
    const float* p2 = P2 + (size_t)bh * Tc * Tc;
    const float* vv = V  + (size_t)bh * Tc * Dc;
    float* out      = Out + (size_t)bh * Tc * Dc;
    const float lam = g_lambda;

    const int m0  = blockIdx.y * 128;
    const int tid = threadIdx.x;
    const int tx  = tid & 15, ty = tid >> 4;

    float acc[8][4];
    #pragma unroll
    for (int i = 0; i < 8; i++)
        #pragma unroll
        for (int j = 0; j < 4; j++) acc[i][j] = 0.f;

    for (int k0 = 0; k0 < Tc; k0 += 16) {
        #pragma unroll
        for (int l = 0; l < 2; l++) {
            int idx = tid + l * 256;
            int r   = idx >> 2;
            int c4  = (idx & 3) << 2;
            float4 a = *(const float4*)(p1 + (size_t)(m0 + r) * Tc + k0 + c4);
            float4 b = *(const float4*)(p2 + (size_t)(m0 + r) * Tc + k0 + c4);
            Ps[c4+0][r] = a.x - lam * b.x;
            Ps[c4+1][r] = a.y - lam * b.y;
            Ps[c4+2][r] = a.z - lam * b.z;
            Ps[c4+3][r] = a.w - lam * b.w;
        }
        {
            int rv = tid >> 4;                 // 0..15 (k row)
            int cv = (tid & 15) << 2;          // 0..60
            *(float4*)&Vs[rv][cv] = *(const float4*)(vv + (k0 + rv) * Dc + cv);
        }
        __syncthreads();

        #pragma unroll
        for (int kk = 0; kk < 16; kk++) {
            float ra[8], rb[4];
            #pragma unroll
            for (int i = 0; i < 8; i++) ra[i] = Ps[kk][ty * 8 + i];
            #pragma unroll
            for (int j = 0; j < 4; j++) rb[j] = Vs[kk][tx * 4 + j];
            #pragma unroll
            for (int i = 0; i < 8; i++)
                #pragma unroll
                for (int j = 0; j < 4; j++) acc[i][j] += ra[i] * rb[j];
        }
        __syncthreads();
    }

    #pragma unroll
    for (int i = 0; i < 8; i++) {
        float4 v4; v4.x = acc[i][0]; v4.y = acc[i][1]; v4.z = acc[i][2]; v4.w = acc[i][3];
        *(float4*)(out + (size_t)(m0 + ty * 8 + i) * Dc + tx * 4) = v4;
    }
}

// -------------------------------------------------------------------------
// RMSNorm over D + affine + (1-lambda_init), and transpose to [B,T,H*D].
// One warp per (b,h,t) row of 64 elements.
// -------------------------------------------------------------------------
__global__ __launch_bounds__(256) void rmsnorm_k(
    const float* __restrict__ X, const float* __restrict__ w, float* __restrict__ O)
{
    int gw   = (blockIdx.x * blockDim.x + threadIdx.x) >> 5;  // row index, exact grid
    int lane = threadIdx.x & 31;

    const float* xr = X + (size_t)gw * Dc;
    float a = xr[lane], b = xr[lane + 32];
    float ss = a * a + b * b;
    #pragma unroll
    for (int o = 16; o; o >>= 1) ss += __shfl_xor_sync(0xffffffffu, ss, o);
    float r = rsqrtf(ss * (1.0f / Dc) + EPSc) * (1.0f - LAMBDA_INIT);

    int bh = gw >> 11;             // / Tc
    int t  = gw & (Tc - 1);
    int bb = bh >> 4, h = bh & (Hc - 1);
    float* o = O + ((size_t)(bb * Tc + t)) * Ec + h * Dc;
    o[lane]      = a * r * w[lane];
    o[lane + 32] = b * r * w[lane + 32];
}

// -------------------------------------------------------------------------
extern "C" void kernel_launch(void* const* d_in, const int* in_sizes, int n_in,
                              void* d_out, int out_size)
{
    const float* noisy = (const float*)d_in[0];
    const float* x     = (const float*)d_in[1];
    const float* Wq1   = (const float*)d_in[2];
    const float* Wk1   = (const float*)d_in[3];
    const float* Wq2   = (const float*)d_in[4];
    const float* Wk2   = (const float*)d_in[5];
    const float* Wv    = (const float*)d_in[6];
    const float* Wout  = (const float*)d_in[7];
    const float* lq1   = (const float*)d_in[8];
    const float* lk1   = (const float*)d_in[9];
    const float* lq2   = (const float*)d_in[10];
    const float* lk2   = (const float*)d_in[11];
    const float* slw   = (const float*)d_in[12];
    float* out = (float*)d_out;

    void *q1p, *k1p, *q2p, *k2p, *vp, *s1p, *s2p, *attnp;
    cudaGetSymbolAddress(&q1p, g_q1);
    cudaGetSymbolAddress(&k1p, g_k1);
    cudaGetSymbolAddress(&q2p, g_q2);
    cudaGetSymbolAddress(&k2p, g_k2);
    cudaGetSymbolAddress(&vp,  g_v);
    cudaGetSymbolAddress(&s1p, g_s1);
    cudaGetSymbolAddress(&s2p, g_s2);
    cudaGetSymbolAddress(&attnp, g_attn);

    lambda_kernel<<<1, 64>>>(lq1, lk1, lq2, lk2);

    const dim3 blk(256);
    const float scl = 0.125f;  // D^-0.5

    // Projections: [4096,1024] x [1024,1024]^T -> head-split [B,H,T,D]
    dim3 gproj(Ec / 128, Mtok / 128, 1);
    sgemm_nt<<<gproj, blk>>>(noisy, Wq1, (float*)q1p, Ec, 0, 0, 0, scl, 1);
    sgemm_nt<<<gproj, blk>>>(noisy, Wk1, (float*)k1p, Ec, 0, 0, 0, 1.f, 1);
    sgemm_nt<<<gproj, blk>>>(x,     Wq2, (float*)q2p, Ec, 0, 0, 0, scl, 1);
    sgemm_nt<<<gproj, blk>>>(x,     Wk2, (float*)k2p, Ec, 0, 0, 0, 1.f, 1);
    sgemm_nt<<<gproj, blk>>>(noisy, Wv,  (float*)vp,  Ec, 0, 0, 0, 1.f, 1);

    // Scores: per-(b,h) [2048,64] x [2048,64]^T -> [2048,2048]
    dim3 gsc(Tc / 128, Tc / 128, BHc);
    sgemm_nt<<<gsc, blk>>>((const float*)q1p, (const float*)k1p, (float*)s1p, Dc,
                           (long long)Tc * Dc, (long long)Tc * Dc, (long long)Tc * Tc, 1.f, 0);
    sgemm_nt<<<gsc, blk>>>((const float*)q2p, (const float*)k2p, (float*)s2p, Dc,
                           (long long)Tc * Dc, (long long)Tc * Dc, (long long)Tc * Tc, 1.f, 0);

    // Softmax (in place)
    softmax_rows<<<BHc * Tc, blk>>>((float*)s1p);
    softmax_rows<<<BHc * Tc, blk>>>((float*)s2p);

    // PV with fused a1 - lam*a2 (reuse g_q1 as [B,H,T,D] output)
    dim3 gpv(1, Tc / 128, BHc);
    gemm_pv<<<gpv, blk>>>((const float*)s1p, (const float*)s2p, (const float*)vp, (float*)q1p);

    // RMSNorm + transpose to [B,T,E]
    rmsnorm_k<<<BHc * Tc / 8, blk>>>((const float*)q1p, slw, (float*)attnp);

    // Output projection -> d_out
    dim3 gout(Ec / 128, Mtok / 128, 1);
    sgemm_nt<<<gout, blk>>>((const float*)attnp, Wout, out, Ec, 0, 0, 0, 1.f, 0);
}

// round 4
// speedup vs baseline: 1.7457x; 1.7457x over previous
#include <cuda_runtime.h>
#include <math.h>

// Problem constants
constexpr int Bc   = 2;
constexpr int Tc   = 2048;
constexpr int Ec   = 1024;
constexpr int Hc   = 16;
constexpr int Dc   = 64;
constexpr int BHc  = Bc * Hc;      // 32
constexpr int Mtok = Bc * Tc;      // 4096
constexpr float LAMBDA_INIT = 0.4707130183435843f;  // 0.8 - 0.6*exp(-0.6)
constexpr float EPSc = 1e-5f;

// Scratch (device globals: allocation-free rule)
__device__ float g_q1[BHc * Tc * Dc];
__device__ float g_k1[BHc * Tc * Dc];
__device__ float g_q2[BHc * Tc * Dc];
__device__ float g_k2[BHc * Tc * Dc];
__device__ float g_v [BHc * Tc * Dc];
__device__ float g_s1[(size_t)BHc * Tc * Tc];   // 512 MB
__device__ float g_s2[(size_t)BHc * Tc * Tc];   // 512 MB
__device__ float g_attn[(size_t)Mtok * Ec];
__device__ float g_lambda;

// -------------------------------------------------------------------------
__device__ __forceinline__ unsigned f2tf(float f) {
    unsigned u;
    asm("cvt.rna.tf32.f32 %0, %1;" : "=r"(u) : "f"(f));
    return u;
}

__device__ __forceinline__ void mma8(float* c, const unsigned* a, const unsigned* b) {
    asm volatile(
        "mma.sync.aligned.m16n8k8.row.col.f32.tf32.tf32.f32 "
        "{%0,%1,%2,%3}, {%4,%5,%6,%7}, {%8,%9}, {%0,%1,%2,%3};"
        : "+f"(c[0]), "+f"(c[1]), "+f"(c[2]), "+f"(c[3])
        : "r"(a[0]), "r"(a[1]), "r"(a[2]), "r"(a[3]), "r"(b[0]), "r"(b[1]));
}

// -------------------------------------------------------------------------
__global__ void lambda_kernel(const float* __restrict__ lq1, const float* __restrict__ lk1,
                              const float* __restrict__ lq2, const float* __restrict__ lk2)
{
    __shared__ float s1[64], s2[64];
    int t = threadIdx.x;
    s1[t] = lq1[t] * lk1[t];
    s2[t] = lq2[t] * lk2[t];
    __syncthreads();
    if (t == 0) {
        float a = 0.f, b = 0.f;
        #pragma unroll
        for (int i = 0; i < 64; i++) { a += s1[i]; b += s2[i]; }
        g_lambda = expf(a) - expf(b) + LAMBDA_INIT;
    }
}

// -------------------------------------------------------------------------
// tf32 tensor-core NT GEMM: C[m,n] = scale * sum_k A[m,k]*Bw[n,k]
// Block tile 128x128xBK16, 256 threads, 8 warps (2 in m x 4 in n),
// warp tile 64x32 (4 msub x 4 nsub of m16n8k8).
// out_mode 0: row-major [M,N];  out_mode 1: head-split [B,H,T,D].
// -------------------------------------------------------------------------
constexpr int APAD = 136;   // words per k-row (128 + 8: conflict-free frag reads)

__global__ __launch_bounds__(256, 2) void tgemm_nt(
    const float* __restrict__ A, const float* __restrict__ Bw,
    float* __restrict__ C, int K,
    long long sA, long long sB, long long sC,
    float scale, int out_mode)
{
    __shared__ unsigned As[16 * APAD];
    __shared__ unsigned Bs[16 * APAD];

    const int bz = blockIdx.z;
    A  += (long long)bz * sA;
    Bw += (long long)bz * sB;
    C  += (long long)bz * sC;

    const int m0 = blockIdx.y * 128;
    const int n0 = blockIdx.x * 128;
    const int N  = gridDim.x * 128;
    const int tid  = threadIdx.x;
    const int warp = tid >> 5, lane = tid & 31;
    const int g = lane >> 2, tig = lane & 3;
    const int wm = (warp & 1) * 64;
    const int wn = (warp >> 1) * 32;
    const int lr = tid >> 1;               // loader row 0..127

    float c[4][4][4];
    #pragma unroll
    for (int i = 0; i < 4; i++)
        #pragma unroll
        for (int j = 0; j < 4; j++)
            #pragma unroll
            for (int r = 0; r < 4; r++) c[i][j][r] = 0.f;

    for (int k0 = 0; k0 < K; k0 += 16) {
        #pragma unroll
        for (int j = 0; j < 2; j++) {
            int kk = ((tid & 1) * 2 + j) * 4;   // 0,4,8,12
            float4 va = *(const float4*)(A + (long long)(m0 + lr) * K + k0 + kk);
            As[(kk+0)*APAD + lr] = f2tf(va.x);
            As[(kk+1)*APAD + lr] = f2tf(va.y);
            As[(kk+2)*APAD + lr] = f2tf(va.z);
            As[(kk+3)*APAD + lr] = f2tf(va.w);
            float4 vb = *(const float4*)(Bw + (long long)(n0 + lr) * K + k0 + kk);
            Bs[(kk+0)*APAD + lr] = f2tf(vb.x);
            Bs[(kk+1)*APAD + lr] = f2tf(vb.y);
            Bs[(kk+2)*APAD + lr] = f2tf(vb.z);
            Bs[(kk+3)*APAD + lr] = f2tf(vb.w);
        }
        __syncthreads();

        #pragma unroll
        for (int ks = 0; ks < 16; ks += 8) {
            unsigned af[4][4], bf[4][2];
            #pragma unroll
            for (int i = 0; i < 4; i++) {
                int mb = wm + i * 16 + g;
                af[i][0] = As[(ks+tig  )*APAD + mb];
                af[i][1] = As[(ks+tig  )*APAD + mb + 8];
                af[i][2] = As[(ks+tig+4)*APAD + mb];
                af[i][3] = As[(ks+tig+4)*APAD + mb + 8];
            }
            #pragma unroll
            for (int jn = 0; jn < 4; jn++) {
                int nb = wn + jn * 8 + g;
                bf[jn][0] = Bs[(ks+tig  )*APAD + nb];
                bf[jn][1] = Bs[(ks+tig+4)*APAD + nb];
            }
            #pragma unroll
            for (int i = 0; i < 4; i++)
                #pragma unroll
                for (int jn = 0; jn < 4; jn++)
                    mma8(c[i][jn], af[i], bf[jn]);
        }
        __syncthreads();
    }

    if (out_mode == 0) {
        #pragma unroll
        for (int i = 0; i < 4; i++) {
            int r0 = m0 + wm + i * 16 + g;
            #pragma unroll
            for (int jn = 0; jn < 4; jn++) {
                int col = n0 + wn + jn * 8 + 2 * tig;
                float2 v0 = { c[i][jn][0] * scale, c[i][jn][1] * scale };
                float2 v1 = { c[i][jn][2] * scale, c[i][jn][3] * scale };
                *(float2*)(C + (long long)r0 * N + col)       = v0;
                *(float2*)(C + (long long)(r0 + 8) * N + col) = v1;
            }
        }
    } else {
        #pragma unroll
        for (int i = 0; i < 4; i++) {
            #pragma unroll
            for (int rr = 0; rr < 2; rr++) {
                int m  = m0 + wm + i * 16 + g + rr * 8;
                int bb = m >> 11;
                int t  = m & (Tc - 1);
                #pragma unroll
                for (int jn = 0; jn < 4; jn++) {
                    int col = n0 + wn + jn * 8 + 2 * tig;
                    int h = col >> 6, d = col & (Dc - 1);
                    float2 v = { c[i][jn][rr*2+0] * scale, c[i][jn][rr*2+1] * scale };
                    *(float2*)(C + ((long long)(bb * Hc + h) * Tc + t) * Dc + d) = v;
                }
            }
        }
    }
}

// -------------------------------------------------------------------------
// Row softmax in place. One block per row of length T=2048. 256 threads.
// -------------------------------------------------------------------------
__global__ __launch_bounds__(256) void softmax_rows(float* __restrict__ S)
{
    __shared__ float red[8];
    float* p = S + (size_t)blockIdx.x * Tc;
    const int tid  = threadIdx.x;
    const int lane = tid & 31;
    const int wrp  = tid >> 5;

    float4 v0 = ((const float4*)p)[tid];
    float4 v1 = ((const float4*)p)[tid + 256];

    float m = fmaxf(fmaxf(fmaxf(v0.x, v0.y), fmaxf(v0.z, v0.w)),
                    fmaxf(fmaxf(v1.x, v1.y), fmaxf(v1.z, v1.w)));
    #pragma unroll
    for (int o = 16; o; o >>= 1) m = fmaxf(m, __shfl_xor_sync(0xffffffffu, m, o));
    if (lane == 0) red[wrp] = m;
    __syncthreads();
    m = red[0];
    #pragma unroll
    for (int i = 1; i < 8; i++) m = fmaxf(m, red[i]);
    __syncthreads();

    v0.x = expf(v0.x - m); v0.y = expf(v0.y - m);
    v0.z = expf(v0.z - m); v0.w = expf(v0.w - m);
    v1.x = expf(v1.x - m); v1.y = expf(v1.y - m);
    v1.z = expf(v1.z - m); v1.w = expf(v1.w - m);

    float s = v0.x + v0.y + v0.z + v0.w + v1.x + v1.y + v1.z + v1.w;
    #pragma unroll
    for (int o = 16; o; o >>= 1) s += __shfl_xor_sync(0xffffffffu, s, o);
    if (lane == 0) red[wrp] = s;
    __syncthreads();
    s = red[0];
    #pragma unroll
    for (int i = 1; i < 8; i++) s += red[i];

    float inv = 1.0f / s;
    v0.x *= inv; v0.y *= inv; v0.z *= inv; v0.w *= inv;
    v1.x *= inv; v1.y *= inv; v1.z *= inv; v1.w *= inv;
    ((float4*)p)[tid]       = v0;
    ((float4*)p)[tid + 256] = v1;
}

// -------------------------------------------------------------------------
// PV tensor-core GEMM: Out[bh,m,d] = sum_k (P1[m,k]-lam*P2[m,k]) * V[bh,k,d]
// Block tile 128x64xBK16, 8 warps (4 in m x 2 in n), warp tile 32x32
// (2 msub x 4 nsub of m16n8k8).
// -------------------------------------------------------------------------
constexpr int BPAD = 72;

__global__ __launch_bounds__(256, 2) void tgemm_pv(
    const float* __restrict__ P1, const float* __restrict__ P2,
    const float* __restrict__ V, float* __restrict__ Out)
{
    __shared__ unsigned As[16 * APAD];
    __shared__ unsigned Vs[16 * BPAD];

    const int bh = blockIdx.z;
    const float* p1 = P1 + (size_t)bh * Tc * Tc;
    const float* p2 = P2 + (size_t)bh * Tc * Tc;
    const float* vv = V  + (size_t)bh * Tc * Dc;
    float* out      = Out + (size_t)bh * Tc * Dc;
    const float lam = g_lambda;

    const int m0 = blockIdx.y * 128;
    const int tid  = threadIdx.x;
    const int warp = tid >> 5, lane = tid & 31;
    const int g = lane >> 2, tig = lane & 3;
    const int wm = (warp & 3) * 32;     // 4 warps in m
    const int wn = (warp >> 2) * 32;    // 2 warps in n
    const int lr = tid >> 1;

    float c[2][4][4];
    #pragma unroll
    for (int i = 0; i < 2; i++)
        #pragma unroll
        for (int j = 0; j < 4; j++)
            #pragma unroll
            for (int r = 0; r < 4; r++) c[i][j][r] = 0.f;

    for (int k0 = 0; k0 < Tc; k0 += 16) {
        #pragma unroll
        for (int j = 0; j < 2; j++) {
            int kk = ((tid & 1) * 2 + j) * 4;
            float4 a = *(const float4*)(p1 + (size_t)(m0 + lr) * Tc + k0 + kk);
            float4 b = *(const float4*)(p2 + (size_t)(m0 + lr) * Tc + k0 + kk);
            As[(kk+0)*APAD + lr] = f2tf(a.x - lam * b.x);
            As[(kk+1)*APAD + lr] = f2tf(a.y - lam * b.y);
            As[(kk+2)*APAD + lr] = f2tf(a.z - lam * b.z);
            As[(kk+3)*APAD + lr] = f2tf(a.w - lam * b.w);
        }
        {
            int kr = tid >> 4;             // 0..15
            int nc = (tid & 15) * 4;       // 0..60
            float4 v = *(const float4*)(vv + (size_t)(k0 + kr) * Dc + nc);
            Vs[kr*BPAD + nc + 0] = f2tf(v.x);
            Vs[kr*BPAD + nc + 1] = f2tf(v.y);
            Vs[kr*BPAD + nc + 2] = f2tf(v.z);
            Vs[kr*BPAD + nc + 3] = f2tf(v.w);
        }
        __syncthreads();

        #pragma unroll
        for (int ks = 0; ks < 16; ks += 8) {
            unsigned af[2][4], bf[4][2];
            #pragma unroll
            for (int i = 0; i < 2; i++) {
                int mb = wm + i * 16 + g;
                af[i][0] = As[(ks+tig  )*APAD + mb];
                af[i][1] = As[(ks+tig  )*APAD + mb + 8];
                af[i][2] = As[(ks+tig+4)*APAD + mb];
                af[i][3] = As[(ks+tig+4)*APAD + mb + 8];
            }
            #pragma unroll
            for (int jn = 0; jn < 4; jn++) {
                int nb = wn + jn * 8 + g;
                bf[jn][0] = Vs[(ks+tig  )*BPAD + nb];
                bf[jn][1] = Vs[(ks+tig+4)*BPAD + nb];
            }
            #pragma unroll
            for (int i = 0; i < 2; i++)
                #pragma unroll
                for (int jn = 0; jn < 4; jn++)
                    mma8(c[i][jn], af[i], bf[jn]);
        }
        __syncthreads();
    }

    #pragma unroll
    for (int i = 0; i < 2; i++) {
        int r0 = m0 + wm + i * 16 + g;
        #pragma unroll
        for (int jn = 0; jn < 4; jn++) {
            int col = wn + jn * 8 + 2 * tig;
            float2 v0 = { c[i][jn][0], c[i][jn][1] };
            float2 v1 = { c[i][jn][2], c[i][jn][3] };
            *(float2*)(out + (size_t)r0 * Dc + col)       = v0;
            *(float2*)(out + (size_t)(r0 + 8) * Dc + col) = v1;
        }
    }
}

// -------------------------------------------------------------------------
// RMSNorm over D + affine + (1-lambda_init), transpose to [B,T,H*D].
// -------------------------------------------------------------------------
__global__ __launch_bounds__(256) void rmsnorm_k(
    const float* __restrict__ X, const float* __restrict__ w, float* __restrict__ O)
{
    int gw   = (blockIdx.x * blockDim.x + threadIdx.x) >> 5;
    int lane = threadIdx.x & 31;

    const float* xr = X + (size_t)gw * Dc;
    float a = xr[lane], b = xr[lane + 32];
    float ss = a * a + b * b;
    #pragma unroll
    for (int o = 16; o; o >>= 1) ss += __shfl_xor_sync(0xffffffffu, ss, o);
    float r = rsqrtf(ss * (1.0f / Dc) + EPSc) * (1.0f - LAMBDA_INIT);

    int bh = gw >> 11;
    int t  = gw & (Tc - 1);
    int bb = bh >> 4, h = bh & (Hc - 1);
    float* o = O + ((size_t)(bb * Tc + t)) * Ec + h * Dc;
    o[lane]      = a * r * w[lane];
    o[lane + 32] = b * r * w[lane + 32];
}

// -------------------------------------------------------------------------
extern "C" void kernel_launch(void* const* d_in, const int* in_sizes, int n_in,
                              void* d_out, int out_size)
{
    const float* noisy = (const float*)d_in[0];
    const float* x     = (const float*)d_in[1];
    const float* Wq1   = (const float*)d_in[2];
    const float* Wk1   = (const float*)d_in[3];
    const float* Wq2   = (const float*)d_in[4];
    const float* Wk2   = (const float*)d_in[5];
    const float* Wv    = (const float*)d_in[6];
    const float* Wout  = (const float*)d_in[7];
    const float* lq1   = (const float*)d_in[8];
    const float* lk1   = (const float*)d_in[9];
    const float* lq2   = (const float*)d_in[10];
    const float* lk2   = (const float*)d_in[11];
    const float* slw   = (const float*)d_in[12];
    float* out = (float*)d_out;

    void *q1p, *k1p, *q2p, *k2p, *vp, *s1p, *s2p, *attnp;
    cudaGetSymbolAddress(&q1p, g_q1);
    cudaGetSymbolAddress(&k1p, g_k1);
    cudaGetSymbolAddress(&q2p, g_q2);
    cudaGetSymbolAddress(&k2p, g_k2);
    cudaGetSymbolAddress(&vp,  g_v);
    cudaGetSymbolAddress(&s1p, g_s1);
    cudaGetSymbolAddress(&s2p, g_s2);
    cudaGetSymbolAddress(&attnp, g_attn);

    lambda_kernel<<<1, 64>>>(lq1, lk1, lq2, lk2);

    const dim3 blk(256);
    const float scl = 0.125f;  // D^-0.5

    // Projections: [4096,1024] x [1024,1024]^T -> head-split [B,H,T,D]
    dim3 gproj(Ec / 128, Mtok / 128, 1);
    tgemm_nt<<<gproj, blk>>>(noisy, Wq1, (float*)q1p, Ec, 0, 0, 0, scl, 1);
    tgemm_nt<<<gproj, blk>>>(noisy, Wk1, (float*)k1p, Ec, 0, 0, 0, 1.f, 1);
    tgemm_nt<<<gproj, blk>>>(x,     Wq2, (float*)q2p, Ec, 0, 0, 0, scl, 1);
    tgemm_nt<<<gproj, blk>>>(x,     Wk2, (float*)k2p, Ec, 0, 0, 0, 1.f, 1);
    tgemm_nt<<<gproj, blk>>>(noisy, Wv,  (float*)vp,  Ec, 0, 0, 0, 1.f, 1);

    // Scores: per-(b,h) [2048,64] x [2048,64]^T -> [2048,2048]
    dim3 gsc(Tc / 128, Tc / 128, BHc);
    tgemm_nt<<<gsc, blk>>>((const float*)q1p, (const float*)k1p, (float*)s1p, Dc,
                           (long long)Tc * Dc, (long long)Tc * Dc, (long long)Tc * Tc, 1.f, 0);
    tgemm_nt<<<gsc, blk>>>((const float*)q2p, (const float*)k2p, (float*)s2p, Dc,
                           (long long)Tc * Dc, (long long)Tc * Dc, (long long)Tc * Tc, 1.f, 0);

    // Softmax (in place)
    softmax_rows<<<BHc * Tc, blk>>>((float*)s1p);
    softmax_rows<<<BHc * Tc, blk>>>((float*)s2p);

    // PV with fused a1 - lam*a2 (reuse g_q1 as [B,H,T,D] output)
    dim3 gpv(1, Tc / 128, BHc);
    tgemm_pv<<<gpv, blk>>>((const float*)s1p, (const float*)s2p, (const float*)vp, (float*)q1p);

    // RMSNorm + transpose to [B,T,E]
    rmsnorm_k<<<BHc * Tc / 8, blk>>>((const float*)q1p, slw, (float*)attnp);

    // Output projection -> d_out
    dim3 gout(Ec / 128, Mtok / 128, 1);
    tgemm_nt<<<gout, blk>>>((const float*)attnp, Wout, out, Ec, 0, 0, 0, 1.f, 0);
}

// round 10
// speedup vs baseline: 3.6578x; 2.0953x over previous
#include <cuda_runtime.h>
#include <cuda_fp16.h>
#include <math.h>

// Problem constants
constexpr int Bc   = 2;
constexpr int Tc   = 2048;
constexpr int Ec   = 1024;
constexpr int Hc   = 16;
constexpr int Dc   = 64;
constexpr int BHc  = Bc * Hc;      // 32
constexpr int Mtok = Bc * Tc;      // 4096
constexpr float LAMBDA_INIT = 0.4707130183435843f;  // 0.8 - 0.6*exp(-0.6)
constexpr float EPSc = 1e-5f;

// Scratch (device globals: allocation-free rule)
__device__ __half g_q1h[BHc * Tc * Dc];
__device__ __half g_k1h[BHc * Tc * Dc];
__device__ __half g_q2h[BHc * Tc * Dc];
__device__ __half g_k2h[BHc * Tc * Dc];
__device__ __half g_vh [BHc * Tc * Dc];
__device__ float  g_o1 [BHc * Tc * Dc];
__device__ float  g_o2 [BHc * Tc * Dc];
__device__ __half g_attnh[(size_t)Mtok * Ec];
__device__ float  g_lambda;

// -------------------------------------------------------------------------
__device__ __forceinline__ unsigned pack2(float lo, float hi) {
    __half2 h = __floats2half2_rn(lo, hi);
    return *reinterpret_cast<unsigned*>(&h);
}

// fp16 mma m16n8k16, fp32 accumulate
__device__ __forceinline__ void mma_h(float* c, const unsigned* a, const unsigned* b) {
    asm volatile(
        "mma.sync.aligned.m16n8k16.row.col.f32.f16.f16.f32 "
        "{%0,%1,%2,%3}, {%4,%5,%6,%7}, {%8,%9}, {%0,%1,%2,%3};"
        : "+f"(c[0]), "+f"(c[1]), "+f"(c[2]), "+f"(c[3])
        : "r"(a[0]), "r"(a[1]), "r"(a[2]), "r"(a[3]), "r"(b[0]), "r"(b[1]));
}

// -------------------------------------------------------------------------
__global__ void lambda_kernel(const float* __restrict__ lq1, const float* __restrict__ lk1,
                              const float* __restrict__ lq2, const float* __restrict__ lk2)
{
    __shared__ float s1[64], s2[64];
    int t = threadIdx.x;
    s1[t] = lq1[t] * lk1[t];
    s2[t] = lq2[t] * lk2[t];
    __syncthreads();
    if (t == 0) {
        float a = 0.f, b = 0.f;
        #pragma unroll
        for (int i = 0; i < 64; i++) { a += s1[i]; b += s2[i]; }
        g_lambda = expf(a) - expf(b) + LAMBDA_INIT;
    }
}

// -------------------------------------------------------------------------
// fp16 tensor-core NT GEMM: C[m,n] = scale * sum_k A[m,k]*W[n,k]
// Block 128x128xBK32, 256 threads, 8 warps (2m x 4n), warp 64x32.
// TA = float (convert on load) or __half. MODE 0: float C row-major.
// MODE 1: __half C head-split [B,H,T,D].
// smem layout [kpair][row], row-pad 132 (frag LDS conflict-free: banks 4*tig+g).
// -------------------------------------------------------------------------
template<typename TA, int MODE>
__global__ __launch_bounds__(256, 2) void tgemm(
    const void* __restrict__ Av, const float* __restrict__ Bw,
    void* __restrict__ Cv, int K, float scale)
{
    __shared__ unsigned As2[16 * 132];
    __shared__ unsigned Bs2[16 * 132];

    const int m0 = blockIdx.y * 128;
    const int n0 = blockIdx.x * 128;
    const int N  = gridDim.x * 128;
    const int tid  = threadIdx.x;
    const int warp = tid >> 5, lane = tid & 31;
    const int g = lane >> 2, tig = lane & 3;
    const int wm = (warp & 1) * 64;
    const int wn = (warp >> 1) * 32;

    float c[4][4][4];
    #pragma unroll
    for (int i = 0; i < 4; i++)
        #pragma unroll
        for (int j = 0; j < 4; j++)
            #pragma unroll
            for (int r = 0; r < 4; r++) c[i][j][r] = 0.f;

    for (int k0 = 0; k0 < K; k0 += 32) {
        // ---- load A ----
        if constexpr (sizeof(TA) == 4) {
            const float* A = (const float*)Av;
            #pragma unroll
            for (int l = 0; l < 4; l++) {
                int u = tid + l * 256;
                int row = u >> 3, f4 = u & 7;
                float4 v = *(const float4*)(A + (long long)(m0 + row) * K + k0 + f4 * 4);
                As2[(2*f4+0)*132 + row] = pack2(v.x, v.y);
                As2[(2*f4+1)*132 + row] = pack2(v.z, v.w);
            }
        } else {
            const __half* A = (const __half*)Av;
            #pragma unroll
            for (int l = 0; l < 2; l++) {
                int u = tid + l * 256;
                int row = u >> 2, seg = u & 3;
                uint4 q = *(const uint4*)(A + (long long)(m0 + row) * K + k0 + seg * 8);
                unsigned* d = &As2[(seg*4)*132 + row];
                d[0] = q.x; d[132] = q.y; d[264] = q.z; d[396] = q.w;
            }
        }
        // ---- load B (always float weights) ----
        #pragma unroll
        for (int l = 0; l < 4; l++) {
            int u = tid + l * 256;
            int row = u >> 3, f4 = u & 7;
            float4 v = *(const float4*)(Bw + (long long)(n0 + row) * K + k0 + f4 * 4);
            Bs2[(2*f4+0)*132 + row] = pack2(v.x, v.y);
            Bs2[(2*f4+1)*132 + row] = pack2(v.z, v.w);
        }
        __syncthreads();

        #pragma unroll
        for (int cc = 0; cc < 2; cc++) {
            unsigned af[4][4], bf[4][2];
            #pragma unroll
            for (int i = 0; i < 4; i++) {
                int mb = wm + i * 16 + g;
                af[i][0] = As2[(8*cc+tig  )*132 + mb];
                af[i][1] = As2[(8*cc+tig  )*132 + mb + 8];
                af[i][2] = As2[(8*cc+tig+4)*132 + mb];
                af[i][3] = As2[(8*cc+tig+4)*132 + mb + 8];
            }
            #pragma unroll
            for (int j = 0; j < 4; j++) {
                int nb = wn + j * 8 + g;
                bf[j][0] = Bs2[(8*cc+tig  )*132 + nb];
                bf[j][1] = Bs2[(8*cc+tig+4)*132 + nb];
            }
            #pragma unroll
            for (int i = 0; i < 4; i++)
                #pragma unroll
                for (int j = 0; j < 4; j++)
                    mma_h(c[i][j], af[i], bf[j]);
        }
        __syncthreads();
    }

    if constexpr (MODE == 0) {
        float* C = (float*)Cv;
        #pragma unroll
        for (int i = 0; i < 4; i++) {
            int r0 = m0 + wm + i * 16 + g;
            #pragma unroll
            for (int j = 0; j < 4; j++) {
                int col = n0 + wn + j * 8 + 2 * tig;
                float2 v0 = { c[i][j][0] * scale, c[i][j][1] * scale };
                float2 v1 = { c[i][j][2] * scale, c[i][j][3] * scale };
                *(float2*)(C + (long long)r0 * N + col)       = v0;
                *(float2*)(C + (long long)(r0 + 8) * N + col) = v1;
            }
        }
    } else {
        __half* C = (__half*)Cv;
        #pragma unroll
        for (int i = 0; i < 4; i++)
            #pragma unroll
            for (int rr = 0; rr < 2; rr++) {
                int m  = m0 + wm + i * 16 + g + rr * 8;
                int bb = m >> 11;
                int t  = m & (Tc - 1);
                #pragma unroll
                for (int j = 0; j < 4; j++) {
                    int col = n0 + wn + j * 8 + 2 * tig;
                    int h = col >> 6, d = col & (Dc - 1);
                    __half2 hv = __floats2half2_rn(c[i][j][rr*2+0] * scale,
                                                   c[i][j][rr*2+1] * scale);
                    *(__half2*)(C + ((size_t)(bb * Hc + h) * Tc + t) * Dc + d) = hv;
                }
            }
    }
}

// -------------------------------------------------------------------------
// Fused flash attention (one softmax branch per launch).
// Block: 1 head x 128-query tile, 256 threads, 8 warps (16 q-rows each).
// K/V streamed in 64-key tiles, double-buffered smem + register prefetch.
// Online softmax in registers; P staged per-warp in smem (pad-36, conflict
// free both directions); O accumulated fp32 via mma.
// -------------------------------------------------------------------------
constexpr int QS_OFF = 0;                         // [32 kpair(d)][132] rows
constexpr int KS_OFF = QS_OFF + 32 * 132;         // 2 bufs x [32 kpair(d)][68] keys
constexpr int VS_OFF = KS_OFF + 2 * 32 * 68;      // 2 bufs x [32 kpair(key)][68] d
constexpr int PS_OFF = VS_OFF + 2 * 32 * 68;      // 8 warps x [16 rows][36]
constexpr int FA_SMEM_UINTS = PS_OFF + 8 * 16 * 36;

__global__ __launch_bounds__(256) void flash_attn_h(
    const __half* __restrict__ Qg, const __half* __restrict__ Kg,
    const __half* __restrict__ Vg, float* __restrict__ Og)
{
    extern __shared__ unsigned sm[];
    const int bh = blockIdx.y, qt = blockIdx.x;
    const int tid = threadIdx.x, lane = tid & 31, warp = tid >> 5;
    const int g = lane >> 2, tig = lane & 3;
    const int wm = warp * 16;

    unsigned* Qs = sm + QS_OFF;
    unsigned* Ps = sm + PS_OFF + warp * (16 * 36);

    const __half* Qp = Qg + ((size_t)bh * Tc + qt * 128) * Dc;
    const __half* Kp = Kg + (size_t)bh * Tc * Dc;
    const __half* Vp = Vg + (size_t)bh * Tc * Dc;

    // Q tile -> smem [kpair(d)][row]
    #pragma unroll
    for (int l = 0; l < 4; l++) {
        int u = tid + l * 256;
        int row = u >> 3, seg = u & 7;
        uint4 q = *(const uint4*)(Qp + (size_t)row * Dc + seg * 8);
        unsigned* d = Qs + (seg * 4) * 132 + row;
        d[0] = q.x; d[132] = q.y; d[264] = q.z; d[396] = q.w;
    }

    // K prefetch regs: [kpair(d)][key]  (no transpose: pack along d)
    // V prefetch regs: need [kpair(key)][d] -> read key-pair, interleave halves
    uint4 kr[2], va4, vb4;
    const int kkey = tid >> 3, kseg = tid & 7;        // K loader coords (2 iters)
    const int vpair = tid >> 3, vseg = tid & 7;       // V loader coords (1 iter)

    auto ldkv = [&](int kt) {
        const __half* kb = Kp + (size_t)kt * 64 * Dc;
        const __half* vb = Vp + (size_t)kt * 64 * Dc;
        kr[0] = *(const uint4*)(kb + (size_t)kkey * Dc + kseg * 8);
        kr[1] = *(const uint4*)(kb + (size_t)(kkey + 32) * Dc + kseg * 8);
        va4   = *(const uint4*)(vb + (size_t)(2 * vpair)     * Dc + vseg * 8);
        vb4   = *(const uint4*)(vb + (size_t)(2 * vpair + 1) * Dc + vseg * 8);
    };
    auto stkv = [&](int buf) {
        unsigned* Kd = sm + KS_OFF + buf * (32 * 68);
        unsigned* Vd = sm + VS_OFF + buf * (32 * 68);
        {
            unsigned* d0 = Kd + (kseg * 4) * 68 + kkey;
            d0[0] = kr[0].x; d0[68] = kr[0].y; d0[136] = kr[0].z; d0[204] = kr[0].w;
            unsigned* d1 = Kd + (kseg * 4) * 68 + kkey + 32;
            d1[0] = kr[1].x; d1[68] = kr[1].y; d1[136] = kr[1].z; d1[204] = kr[1].w;
        }
        {
            const __half* ha = (const __half*)&va4;
            const __half* hb = (const __half*)&vb4;
            unsigned* d = Vd + vpair * 68 + vseg * 8;
            #pragma unroll
            for (int i = 0; i < 8; i++) {
                __half2 h = __halves2half2(ha[i], hb[i]);   // low = even key
                d[i] = *reinterpret_cast<unsigned*>(&h);
            }
        }
    };

    float o[8][4];
    #pragma unroll
    for (int nd = 0; nd < 8; nd++)
        #pragma unroll
        for (int r = 0; r < 4; r++) o[nd][r] = 0.f;
    float m0 = -1e30f, m1 = -1e30f, s0 = 0.f, s1 = 0.f;

    ldkv(0);
    stkv(0);
    __syncthreads();

    for (int kt = 0; kt < Tc / 64; kt++) {
        const int buf = kt & 1;
        if (kt + 1 < Tc / 64) ldkv(kt + 1);   // overlap DRAM with compute

        const unsigned* Kb = sm + KS_OFF + buf * (32 * 68);
        const unsigned* Vb = sm + VS_OFF + buf * (32 * 68);

        // ---- S = Q . K^T  (m16 x n64 x k64) ----
        float sc[8][4];
        #pragma unroll
        for (int ns = 0; ns < 8; ns++)
            #pragma unroll
            for (int r = 0; r < 4; r++) sc[ns][r] = 0.f;

        #pragma unroll
        for (int c = 0; c < 4; c++) {
            unsigned a[4];
            a[0] = Qs[(8*c+tig  )*132 + wm + g];
            a[1] = Qs[(8*c+tig  )*132 + wm + g + 8];
            a[2] = Qs[(8*c+tig+4)*132 + wm + g];
            a[3] = Qs[(8*c+tig+4)*132 + wm + g + 8];
            #pragma unroll
            for (int ns = 0; ns < 8; ns++) {
                unsigned b[2] = { Kb[(8*c+tig  )*68 + ns*8 + g],
                                  Kb[(8*c+tig+4)*68 + ns*8 + g] };
                mma_h(sc[ns], a, b);
            }
        }

        // ---- online softmax (rows g and g+8) ----
        float mx0 = -1e30f, mx1 = -1e30f;
        #pragma unroll
        for (int j = 0; j < 8; j++) {
            mx0 = fmaxf(mx0, fmaxf(sc[j][0], sc[j][1]));
            mx1 = fmaxf(mx1, fmaxf(sc[j][2], sc[j][3]));
        }
        mx0 = fmaxf(mx0, __shfl_xor_sync(0xffffffffu, mx0, 1));
        mx0 = fmaxf(mx0, __shfl_xor_sync(0xffffffffu, mx0, 2));
        mx1 = fmaxf(mx1, __shfl_xor_sync(0xffffffffu, mx1, 1));
        mx1 = fmaxf(mx1, __shfl_xor_sync(0xffffffffu, mx1, 2));
        float nm0 = fmaxf(m0, mx0), nm1 = fmaxf(m1, mx1);
        float cor0 = __expf(m0 - nm0), cor1 = __expf(m1 - nm1);
        m0 = nm0; m1 = nm1;

        __syncwarp();
        float sum0 = 0.f, sum1 = 0.f;
        #pragma unroll
        for (int j = 0; j < 8; j++) {
            float p0 = __expf(sc[j][0] - nm0);
            float p1 = __expf(sc[j][1] - nm0);
            float p2 = __expf(sc[j][2] - nm1);
            float p3 = __expf(sc[j][3] - nm1);
            sum0 += p0 + p1; sum1 += p2 + p3;
            Ps[ g     * 36 + 4*j + tig] = pack2(p0, p1);
            Ps[(g+8)  * 36 + 4*j + tig] = pack2(p2, p3);
        }
        sum0 += __shfl_xor_sync(0xffffffffu, sum0, 1);
        sum0 += __shfl_xor_sync(0xffffffffu, sum0, 2);
        sum1 += __shfl_xor_sync(0xffffffffu, sum1, 1);
        sum1 += __shfl_xor_sync(0xffffffffu, sum1, 2);
        s0 = s0 * cor0 + sum0;
        s1 = s1 * cor1 + sum1;

        #pragma unroll
        for (int nd = 0; nd < 8; nd++) {
            o[nd][0] *= cor0; o[nd][1] *= cor0;
            o[nd][2] *= cor1; o[nd][3] *= cor1;
        }
        __syncwarp();

        // ---- O += P . V  (m16 x n64 x k64) ----
        #pragma unroll
        for (int c = 0; c < 4; c++) {
            unsigned a[4] = { Ps[ g    *36 + 8*c + tig],
                              Ps[(g+8) *36 + 8*c + tig],
                              Ps[ g    *36 + 8*c + tig + 4],
                              Ps[(g+8) *36 + 8*c + tig + 4] };
            #pragma unroll
            for (int nd = 0; nd < 8; nd++) {
                unsigned b[2] = { Vb[(8*c+tig  )*68 + nd*8 + g],
                                  Vb[(8*c+tig+4)*68 + nd*8 + g] };
                mma_h(o[nd], a, b);
            }
        }

        if (kt + 1 < Tc / 64) stkv(buf ^ 1);
        __syncthreads();
    }

    // ---- normalize + write O ----
    float inv0 = 1.0f / s0, inv1 = 1.0f / s1;
    int row0 = qt * 128 + wm + g;
    float* ob = Og + (size_t)bh * Tc * Dc;
    #pragma unroll
    for (int nd = 0; nd < 8; nd++) {
        int col = nd * 8 + 2 * tig;
        float2 v0 = { o[nd][0] * inv0, o[nd][1] * inv0 };
        float2 v1 = { o[nd][2] * inv1, o[nd][3] * inv1 };
        *(float2*)(ob + (size_t)row0 * Dc + col)       = v0;
        *(float2*)(ob + (size_t)(row0 + 8) * Dc + col) = v1;
    }
}

// -------------------------------------------------------------------------
// merge O1 - lam*O2, RMSNorm over D, affine, (1-lambda_init), transpose,
// write fp16 for the output projection.  One warp per (bh,t) row.
// -------------------------------------------------------------------------
__global__ __launch_bounds__(256) void merge_rms(
    const float* __restrict__ o1, const float* __restrict__ o2,
    const float* __restrict__ w, __half* __restrict__ O)
{
    int r    = blockIdx.x * 8 + (threadIdx.x >> 5);
    int lane = threadIdx.x & 31;
    float lam = g_lambda;

    const float* p1 = o1 + (size_t)r * Dc;
    const float* p2 = o2 + (size_t)r * Dc;
    float a = p1[lane]      - lam * p2[lane];
    float b = p1[lane + 32] - lam * p2[lane + 32];
    float ss = a * a + b * b;
    #pragma unroll
    for (int o = 16; o; o >>= 1) ss += __shfl_xor_sync(0xffffffffu, ss, o);
    float rr = rsqrtf(ss * (1.0f / Dc) + EPSc) * (1.0f - LAMBDA_INIT);

    int bh = r >> 11, t = r & (Tc - 1);
    int bb = bh >> 4, h = bh & (Hc - 1);
    __half* o = O + ((size_t)(bb * Tc + t)) * Ec + h * Dc;
    o[lane]      = __float2half(a * rr * w[lane]);
    o[lane + 32] = __float2half(b * rr * w[lane + 32]);
}

// -------------------------------------------------------------------------
extern "C" void kernel_launch(void* const* d_in, const int* in_sizes, int n_in,
                              void* d_out, int out_size)
{
    const float* noisy = (const float*)d_in[0];
    const float* x     = (const float*)d_in[1];
    const float* Wq1   = (const float*)d_in[2];
    const float* Wk1   = (const float*)d_in[3];
    const float* Wq2   = (const float*)d_in[4];
    const float* Wk2   = (const float*)d_in[5];
    const float* Wv    = (const float*)d_in[6];
    const float* Wout  = (const float*)d_in[7];
    const float* lq1   = (const float*)d_in[8];
    const float* lk1   = (const float*)d_in[9];
    const float* lq2   = (const float*)d_in[10];
    const float* lk2   = (const float*)d_in[11];
    const float* slw   = (const float*)d_in[12];
    float* out = (float*)d_out;

    void *q1p, *k1p, *q2p, *k2p, *vp, *o1p, *o2p, *attnp;
    cudaGetSymbolAddress(&q1p, g_q1h);
    cudaGetSymbolAddress(&k1p, g_k1h);
    cudaGetSymbolAddress(&q2p, g_q2h);
    cudaGetSymbolAddress(&k2p, g_k2h);
    cudaGetSymbolAddress(&vp,  g_vh);
    cudaGetSymbolAddress(&o1p, g_o1);
    cudaGetSymbolAddress(&o2p, g_o2);
    cudaGetSymbolAddress(&attnp, g_attnh);

    static bool attr_set = false;
    if (!attr_set) {
        cudaFuncSetAttribute(flash_attn_h, cudaFuncAttributeMaxDynamicSharedMemorySize,
                             FA_SMEM_UINTS * 4);
        attr_set = true;
    }

    lambda_kernel<<<1, 64>>>(lq1, lk1, lq2, lk2);

    const dim3 blk(256);
    const float scl = 0.125f;  // D^-0.5

    // Projections: [4096,1024] x [1024,1024]^T -> head-split fp16 [B,H,T,D]
    dim3 gproj(Ec / 128, Mtok / 128);
    tgemm<float, 1><<<gproj, blk>>>(noisy, Wq1, q1p, Ec, scl);
    tgemm<float, 1><<<gproj, blk>>>(noisy, Wk1, k1p, Ec, 1.f);
    tgemm<float, 1><<<gproj, blk>>>(x,     Wq2, q2p, Ec, scl);
    tgemm<float, 1><<<gproj, blk>>>(x,     Wk2, k2p, Ec, 1.f);
    tgemm<float, 1><<<gproj, blk>>>(noisy, Wv,  vp,  Ec, 1.f);

    // Fused flash attention, one branch per launch
    dim3 gfa(Tc / 128, BHc);
    flash_attn_h<<<gfa, blk, FA_SMEM_UINTS * 4>>>((const __half*)q1p, (const __half*)k1p,
                                                  (const __half*)vp, (float*)o1p);
    flash_attn_h<<<gfa, blk, FA_SMEM_UINTS * 4>>>((const __half*)q2p, (const __half*)k2p,
                                                  (const __half*)vp, (float*)o2p);

    // Merge + RMSNorm -> fp16 [B,T,E]
    merge_rms<<<BHc * Tc / 8, blk>>>((const float*)o1p, (const float*)o2p, slw, (__half*)attnp);

    // Output projection -> d_out (fp32)
    dim3 gout(Ec / 128, Mtok / 128);
    tgemm<__half, 0><<<gout, blk>>>(attnp, Wout, out, Ec, 1.f);
}

// round 11
// speedup vs baseline: 4.6121x; 1.2609x over previous
#include <cuda_runtime.h>
#include <cuda_fp16.h>
#include <math.h>

// Problem constants
constexpr int Bc   = 2;
constexpr int Tc   = 2048;
constexpr int Ec   = 1024;
constexpr int Hc   = 16;
constexpr int Dc   = 64;
constexpr int BHc  = Bc * Hc;      // 32
constexpr int Mtok = Bc * Tc;      // 4096
constexpr float LAMBDA_INIT = 0.4707130183435843f;  // 0.8 - 0.6*exp(-0.6)
constexpr float EPSc = 1e-5f;
constexpr size_t SLAB = (size_t)BHc * Tc * Dc;      // 4M elems

// Scratch (device globals: allocation-free rule)
__device__ __half g_nh[(size_t)Mtok * Ec];
__device__ __half g_xh[(size_t)Mtok * Ec];
__device__ __half g_wh[6 * (size_t)Ec * Ec];
__device__ __half g_projh[5 * SLAB];          // q1,k1,q2,k2,v
__device__ float  g_o1 [SLAB];
__device__ float  g_o2 [SLAB];
__device__ __half g_attnh[(size_t)Mtok * Ec];
__device__ float  g_lambda;

// -------------------------------------------------------------------------
__device__ __forceinline__ unsigned pack2(float lo, float hi) {
    __half2 h = __floats2half2_rn(lo, hi);
    return *reinterpret_cast<unsigned*>(&h);
}

// fp16 mma m16n8k16, fp32 accumulate
__device__ __forceinline__ void mma_h(float* c, const unsigned* a, const unsigned* b) {
    asm volatile(
        "mma.sync.aligned.m16n8k16.row.col.f32.f16.f16.f32 "
        "{%0,%1,%2,%3}, {%4,%5,%6,%7}, {%8,%9}, {%0,%1,%2,%3};"
        : "+f"(c[0]), "+f"(c[1]), "+f"(c[2]), "+f"(c[3])
        : "r"(a[0]), "r"(a[1]), "r"(a[2]), "r"(a[3]), "r"(b[0]), "r"(b[1]));
}

__device__ __forceinline__ void cp16(unsigned saddr, const void* g) {
    asm volatile("cp.async.cg.shared.global [%0], [%1], 16;\n" :: "r"(saddr), "l"(g));
}
__device__ __forceinline__ void cp_commit() { asm volatile("cp.async.commit_group;\n"); }
template<int N> __device__ __forceinline__ void cp_wait() {
    asm volatile("cp.async.wait_group %0;\n" :: "n"(N));
}
__device__ __forceinline__ void ldmx4(unsigned* r, unsigned addr) {
    asm volatile("ldmatrix.sync.aligned.m8n8.x4.shared.b16 {%0,%1,%2,%3}, [%4];"
        : "=r"(r[0]), "=r"(r[1]), "=r"(r[2]), "=r"(r[3]) : "r"(addr));
}

// -------------------------------------------------------------------------
__global__ void lambda_kernel(const float* __restrict__ lq1, const float* __restrict__ lk1,
                              const float* __restrict__ lq2, const float* __restrict__ lk2)
{
    __shared__ float s1[64], s2[64];
    int t = threadIdx.x;
    s1[t] = lq1[t] * lk1[t];
    s2[t] = lq2[t] * lk2[t];
    __syncthreads();
    if (t == 0) {
        float a = 0.f, b = 0.f;
        #pragma unroll
        for (int i = 0; i < 64; i++) { a += s1[i]; b += s2[i]; }
        g_lambda = expf(a) - expf(b) + LAMBDA_INIT;
    }
}

// -------------------------------------------------------------------------
// Convert all fp32 operands to fp16 once. z selects the tensor.
// q-scaling (D^-0.5 = 0.125, exact) folded into Wq1/Wq2.
// -------------------------------------------------------------------------
__global__ __launch_bounds__(256) void cvt_all(
    const float* nsy, const float* xx,
    const float* w0, const float* w1, const float* w2,
    const float* w3, const float* w4, const float* w5,
    __half* nh, __half* xh, __half* wh)
{
    int z = blockIdx.y;
    const float* s; __half* d; int n; float scl = 1.f;
    switch (z) {
        case 0: s = nsy; d = nh; n = Mtok * Ec; break;
        case 1: s = xx;  d = xh; n = Mtok * Ec; break;
        case 2: s = w0; d = wh + 0 * (size_t)Ec * Ec; n = Ec * Ec; scl = 0.125f; break;
        case 3: s = w1; d = wh + 1 * (size_t)Ec * Ec; n = Ec * Ec; break;
        case 4: s = w2; d = wh + 2 * (size_t)Ec * Ec; n = Ec * Ec; scl = 0.125f; break;
        case 5: s = w3; d = wh + 3 * (size_t)Ec * Ec; n = Ec * Ec; break;
        case 6: s = w4; d = wh + 4 * (size_t)Ec * Ec; n = Ec * Ec; break;
        default: s = w5; d = wh + 5 * (size_t)Ec * Ec; n = Ec * Ec; break;
    }
    int n4 = n >> 2;
    for (int i = blockIdx.x * blockDim.x + threadIdx.x; i < n4; i += gridDim.x * blockDim.x) {
        float4 v = ((const float4*)s)[i];
        ((__half2*)d)[2*i]   = __floats2half2_rn(v.x * scl, v.y * scl);
        ((__half2*)d)[2*i+1] = __floats2half2_rn(v.z * scl, v.w * scl);
    }
}

// -------------------------------------------------------------------------
// Pipelined fp16 NT HGEMM: C[m,n] = scale * sum_k A[m,k]*W[n,k]
// Block 128x128x(k32), 256 threads, 8 warps (2m x 4n), warp 64x32.
// cp.async 3-stage pipeline; smem rows padded to 80B (conflict-free ldmatrix).
// MODE 0: fp32 C row-major (single z).  MODE 1: fp16 head-split [B,H,T,D],
//   z in [0,5): {q1,k1,q2,k2,v}, A = noisy (z!=2,3) or x, W = wh + z*E*E.
// -------------------------------------------------------------------------
constexpr int TILEB = 128 * 80;                 // bytes per operand tile stage
constexpr int HG_SMEM = 3 * 2 * TILEB;          // 61440 B

template<int MODE>
__global__ __launch_bounds__(256, 2) void hgemm(
    const __half* __restrict__ Nbase, const __half* __restrict__ Xbase,
    const __half* __restrict__ Wbase, float* __restrict__ Cf,
    __half* __restrict__ Cproj, int K, float scale)
{
    extern __shared__ char dynsm[];
    const unsigned sbase = (unsigned)__cvta_generic_to_shared(dynsm);

    const int z = blockIdx.z;
    const __half* Aop;
    const __half* Wop;
    __half* Cp = nullptr;
    if (MODE == 1) {
        Aop = (z == 2 || z == 3) ? Xbase : Nbase;
        Wop = Wbase + (size_t)z * Ec * Ec;
        Cp  = Cproj + (size_t)z * SLAB;
    } else {
        Aop = Nbase;
        Wop = Wbase;
    }

    const int m0 = blockIdx.y * 128;
    const int n0 = blockIdx.x * 128;
    const int N  = gridDim.x * 128;
    const int tid  = threadIdx.x;
    const int warp = tid >> 5, lane = tid & 31;
    const int g = lane >> 2, tig = lane & 3;
    const int wm = (warp & 1) * 64;
    const int wn = (warp >> 1) * 32;

    auto load_stage = [&](int kt, int s) {
        unsigned sa = sbase + s * (2 * TILEB);
        unsigned sb = sa + TILEB;
        const __half* Ap = Aop + (size_t)m0 * K + kt * 32;
        const __half* Wp = Wop + (size_t)n0 * K + kt * 32;
        #pragma unroll
        for (int j2 = 0; j2 < 2; j2++) {
            int cid = tid + j2 * 256;
            int row = cid >> 2, cc = cid & 3;
            cp16(sa + row * 80 + cc * 16, Ap + (size_t)row * K + cc * 8);
            cp16(sb + row * 80 + cc * 16, Wp + (size_t)row * K + cc * 8);
        }
    };

    float acc[4][4][4];
    #pragma unroll
    for (int i = 0; i < 4; i++)
        #pragma unroll
        for (int j = 0; j < 4; j++)
            #pragma unroll
            for (int r = 0; r < 4; r++) acc[i][j][r] = 0.f;

    const int KT = K / 32;
    load_stage(0, 0); cp_commit();
    load_stage(1, 1); cp_commit();

    for (int kt = 0; kt < KT; kt++) {
        cp_wait<1>();
        __syncthreads();
        if (kt + 2 < KT) load_stage(kt + 2, (kt + 2) % 3);
        cp_commit();

        const int s = kt % 3;
        unsigned aS = sbase + s * (2 * TILEB);
        unsigned bS = aS + TILEB;

        #pragma unroll
        for (int kc = 0; kc < 2; kc++) {
            unsigned a[4][4], b[4][2];
            #pragma unroll
            for (int i = 0; i < 4; i++) {
                int row = wm + i * 16 + ((lane >> 3) & 1) * 8 + (lane & 7);
                int ch  = kc * 2 + (lane >> 4);
                ldmx4(a[i], aS + row * 80 + ch * 16);
            }
            #pragma unroll
            for (int jp = 0; jp < 2; jp++) {
                int mat = lane >> 3;
                int row = wn + jp * 16 + (mat >> 1) * 8 + (lane & 7);
                int ch  = kc * 2 + (mat & 1);
                ldmx4(&b[2 * jp][0], bS + row * 80 + ch * 16);
            }
            #pragma unroll
            for (int i = 0; i < 4; i++)
                #pragma unroll
                for (int j = 0; j < 4; j++)
                    mma_h(acc[i][j], a[i], b[j]);
        }
        __syncthreads();
    }

    if (MODE == 0) {
        #pragma unroll
        for (int i = 0; i < 4; i++) {
            int r0 = m0 + wm + i * 16 + g;
            #pragma unroll
            for (int j = 0; j < 4; j++) {
                int col = n0 + wn + j * 8 + 2 * tig;
                float2 v0 = { acc[i][j][0] * scale, acc[i][j][1] * scale };
                float2 v1 = { acc[i][j][2] * scale, acc[i][j][3] * scale };
                *(float2*)(Cf + (size_t)r0 * N + col)       = v0;
                *(float2*)(Cf + (size_t)(r0 + 8) * N + col) = v1;
            }
        }
    } else {
        #pragma unroll
        for (int i = 0; i < 4; i++)
            #pragma unroll
            for (int rr = 0; rr < 2; rr++) {
                int m  = m0 + wm + i * 16 + g + rr * 8;
                int bb = m >> 11;
                int t  = m & (Tc - 1);
                #pragma unroll
                for (int j = 0; j < 4; j++) {
                    int col = n0 + wn + j * 8 + 2 * tig;
                    int h = col >> 6, d = col & (Dc - 1);
                    __half2 hv = __floats2half2_rn(acc[i][j][rr*2+0], acc[i][j][rr*2+1]);
                    *(__half2*)(Cp + ((size_t)(bb * Hc + h) * Tc + t) * Dc + d) = hv;
                }
            }
    }
}

// -------------------------------------------------------------------------
// Fused flash attention (one softmax branch per launch).
// Block: 1 head x 128-query tile, 256 threads, 8 warps (16 q-rows each).
// K/V streamed in 64-key tiles, double-buffered smem + register prefetch.
// -------------------------------------------------------------------------
constexpr int QS_OFF = 0;                         // [32 kpair(d)][132] rows
constexpr int KS_OFF = QS_OFF + 32 * 132;         // 2 bufs x [32 kpair(d)][68] keys
constexpr int VS_OFF = KS_OFF + 2 * 32 * 68;      // 2 bufs x [32 kpair(key)][68] d
constexpr int PS_OFF = VS_OFF + 2 * 32 * 68;      // 8 warps x [16 rows][36]
constexpr int FA_SMEM_UINTS = PS_OFF + 8 * 16 * 36;

__global__ __launch_bounds__(256) void flash_attn_h(
    const __half* __restrict__ Qg, const __half* __restrict__ Kg,
    const __half* __restrict__ Vg, float* __restrict__ Og)
{
    extern __shared__ unsigned sm[];
    const int bh = blockIdx.y, qt = blockIdx.x;
    const int tid = threadIdx.x, lane = tid & 31, warp = tid >> 5;
    const int g = lane >> 2, tig = lane & 3;
    const int wm = warp * 16;

    unsigned* Qs = sm + QS_OFF;
    unsigned* Ps = sm + PS_OFF + warp * (16 * 36);

    const __half* Qp = Qg + ((size_t)bh * Tc + qt * 128) * Dc;
    const __half* Kp = Kg + (size_t)bh * Tc * Dc;
    const __half* Vp = Vg + (size_t)bh * Tc * Dc;

    #pragma unroll
    for (int l = 0; l < 4; l++) {
        int u = tid + l * 256;
        int row = u >> 3, seg = u & 7;
        uint4 q = *(const uint4*)(Qp + (size_t)row * Dc + seg * 8);
        unsigned* d = Qs + (seg * 4) * 132 + row;
        d[0] = q.x; d[132] = q.y; d[264] = q.z; d[396] = q.w;
    }

    uint4 kr[2], va4, vb4;
    const int kkey = tid >> 3, kseg = tid & 7;
    const int vpair = tid >> 3, vseg = tid & 7;

    auto ldkv = [&](int kt) {
        const __half* kb = Kp + (size_t)kt * 64 * Dc;
        const __half* vb = Vp + (size_t)kt * 64 * Dc;
        kr[0] = *(const uint4*)(kb + (size_t)kkey * Dc + kseg * 8);
        kr[1] = *(const uint4*)(kb + (size_t)(kkey + 32) * Dc + kseg * 8);
        va4   = *(const uint4*)(vb + (size_t)(2 * vpair)     * Dc + vseg * 8);
        vb4   = *(const uint4*)(vb + (size_t)(2 * vpair + 1) * Dc + vseg * 8);
    };
    auto stkv = [&](int buf) {
        unsigned* Kd = sm + KS_OFF + buf * (32 * 68);
        unsigned* Vd = sm + VS_OFF + buf * (32 * 68);
        {
            unsigned* d0 = Kd + (kseg * 4) * 68 + kkey;
            d0[0] = kr[0].x; d0[68] = kr[0].y; d0[136] = kr[0].z; d0[204] = kr[0].w;
            unsigned* d1 = Kd + (kseg * 4) * 68 + kkey + 32;
            d1[0] = kr[1].x; d1[68] = kr[1].y; d1[136] = kr[1].z; d1[204] = kr[1].w;
        }
        {
            const __half* ha = (const __half*)&va4;
            const __half* hb = (const __half*)&vb4;
            unsigned* d = Vd + vpair * 68 + vseg * 8;
            #pragma unroll
            for (int i = 0; i < 8; i++) {
                __half2 h = __halves2half2(ha[i], hb[i]);
                d[i] = *reinterpret_cast<unsigned*>(&h);
            }
        }
    };

    float o[8][4];
    #pragma unroll
    for (int nd = 0; nd < 8; nd++)
        #pragma unroll
        for (int r = 0; r < 4; r++) o[nd][r] = 0.f;
    float m0 = -1e30f, m1 = -1e30f, s0 = 0.f, s1 = 0.f;

    ldkv(0);
    stkv(0);
    __syncthreads();

    for (int kt = 0; kt < Tc / 64; kt++) {
        const int buf = kt & 1;
        if (kt + 1 < Tc / 64) ldkv(kt + 1);

        const unsigned* Kb = sm + KS_OFF + buf * (32 * 68);
        const unsigned* Vb = sm + VS_OFF + buf * (32 * 68);

        float sc[8][4];
        #pragma unroll
        for (int ns = 0; ns < 8; ns++)
            #pragma unroll
            for (int r = 0; r < 4; r++) sc[ns][r] = 0.f;

        #pragma unroll
        for (int c = 0; c < 4; c++) {
            unsigned a[4];
            a[0] = Qs[(8*c+tig  )*132 + wm + g];
            a[1] = Qs[(8*c+tig  )*132 + wm + g + 8];
            a[2] = Qs[(8*c+tig+4)*132 + wm + g];
            a[3] = Qs[(8*c+tig+4)*132 + wm + g + 8];
            #pragma unroll
            for (int ns = 0; ns < 8; ns++) {
                unsigned b[2] = { Kb[(8*c+tig  )*68 + ns*8 + g],
                                  Kb[(8*c+tig+4)*68 + ns*8 + g] };
                mma_h(sc[ns], a, b);
            }
        }

        float mx0 = -1e30f, mx1 = -1e30f;
        #pragma unroll
        for (int j = 0; j < 8; j++) {
            mx0 = fmaxf(mx0, fmaxf(sc[j][0], sc[j][1]));
            mx1 = fmaxf(mx1, fmaxf(sc[j][2], sc[j][3]));
        }
        mx0 = fmaxf(mx0, __shfl_xor_sync(0xffffffffu, mx0, 1));
        mx0 = fmaxf(mx0, __shfl_xor_sync(0xffffffffu, mx0, 2));
        mx1 = fmaxf(mx1, __shfl_xor_sync(0xffffffffu, mx1, 1));
        mx1 = fmaxf(mx1, __shfl_xor_sync(0xffffffffu, mx1, 2));
        float nm0 = fmaxf(m0, mx0), nm1 = fmaxf(m1, mx1);
        float cor0 = __expf(m0 - nm0), cor1 = __expf(m1 - nm1);
        m0 = nm0; m1 = nm1;

        __syncwarp();
        float sum0 = 0.f, sum1 = 0.f;
        #pragma unroll
        for (int j = 0; j < 8; j++) {
            float p0 = __expf(sc[j][0] - nm0);
            float p1 = __expf(sc[j][1] - nm0);
            float p2 = __expf(sc[j][2] - nm1);
            float p3 = __expf(sc[j][3] - nm1);
            sum0 += p0 + p1; sum1 += p2 + p3;
            Ps[ g     * 36 + 4*j + tig] = pack2(p0, p1);
            Ps[(g+8)  * 36 + 4*j + tig] = pack2(p2, p3);
        }
        sum0 += __shfl_xor_sync(0xffffffffu, sum0, 1);
        sum0 += __shfl_xor_sync(0xffffffffu, sum0, 2);
        sum1 += __shfl_xor_sync(0xffffffffu, sum1, 1);
        sum1 += __shfl_xor_sync(0xffffffffu, sum1, 2);
        s0 = s0 * cor0 + sum0;
        s1 = s1 * cor1 + sum1;

        #pragma unroll
        for (int nd = 0; nd < 8; nd++) {
            o[nd][0] *= cor0; o[nd][1] *= cor0;
            o[nd][2] *= cor1; o[nd][3] *= cor1;
        }
        __syncwarp();

        #pragma unroll
        for (int c = 0; c < 4; c++) {
            unsigned a[4] = { Ps[ g    *36 + 8*c + tig],
                              Ps[(g+8) *36 + 8*c + tig],
                              Ps[ g    *36 + 8*c + tig + 4],
                              Ps[(g+8) *36 + 8*c + tig + 4] };
            #pragma unroll
            for (int nd = 0; nd < 8; nd++) {
                unsigned b[2] = { Vb[(8*c+tig  )*68 + nd*8 + g],
                                  Vb[(8*c+tig+4)*68 + nd*8 + g] };
                mma_h(o[nd], a, b);
            }
        }

        if (kt + 1 < Tc / 64) stkv(buf ^ 1);
        __syncthreads();
    }

    float inv0 = 1.0f / s0, inv1 = 1.0f / s1;
    int row0 = qt * 128 + wm + g;
    float* ob = Og + (size_t)bh * Tc * Dc;
    #pragma unroll
    for (int nd = 0; nd < 8; nd++) {
        int col = nd * 8 + 2 * tig;
        float2 v0 = { o[nd][0] * inv0, o[nd][1] * inv0 };
        float2 v1 = { o[nd][2] * inv1, o[nd][3] * inv1 };
        *(float2*)(ob + (size_t)row0 * Dc + col)       = v0;
        *(float2*)(ob + (size_t)(row0 + 8) * Dc + col) = v1;
    }
}

// -------------------------------------------------------------------------
// merge O1 - lam*O2, RMSNorm over D, affine, (1-lambda_init), transpose,
// write fp16 for the output projection.  One warp per (bh,t) row.
// -------------------------------------------------------------------------
__global__ __launch_bounds__(256) void merge_rms(
    const float* __restrict__ o1, const float* __restrict__ o2,
    const float* __restrict__ w, __half* __restrict__ O)
{
    int r    = blockIdx.x * 8 + (threadIdx.x >> 5);
    int lane = threadIdx.x & 31;
    float lam = g_lambda;

    const float* p1 = o1 + (size_t)r * Dc;
    const float* p2 = o2 + (size_t)r * Dc;
    float a = p1[lane]      - lam * p2[lane];
    float b = p1[lane + 32] - lam * p2[lane + 32];
    float ss = a * a + b * b;
    #pragma unroll
    for (int o = 16; o; o >>= 1) ss += __shfl_xor_sync(0xffffffffu, ss, o);
    float rr = rsqrtf(ss * (1.0f / Dc) + EPSc) * (1.0f - LAMBDA_INIT);

    int bh = r >> 11, t = r & (Tc - 1);
    int bb = bh >> 4, h = bh & (Hc - 1);
    __half* o = O + ((size_t)(bb * Tc + t)) * Ec + h * Dc;
    o[lane]      = __float2half(a * rr * w[lane]);
    o[lane + 32] = __float2half(b * rr * w[lane + 32]);
}

// -------------------------------------------------------------------------
extern "C" void kernel_launch(void* const* d_in, const int* in_sizes, int n_in,
                              void* d_out, int out_size)
{
    const float* noisy = (const float*)d_in[0];
    const float* x     = (const float*)d_in[1];
    const float* Wq1   = (const float*)d_in[2];
    const float* Wk1   = (const float*)d_in[3];
    const float* Wq2   = (const float*)d_in[4];
    const float* Wk2   = (const float*)d_in[5];
    const float* Wv    = (const float*)d_in[6];
    const float* Wout  = (const float*)d_in[7];
    const float* lq1   = (const float*)d_in[8];
    const float* lk1   = (const float*)d_in[9];
    const float* lq2   = (const float*)d_in[10];
    const float* lk2   = (const float*)d_in[11];
    const float* slw   = (const float*)d_in[12];
    float* out = (float*)d_out;

    void *nhp, *xhp, *whp, *projp, *o1p, *o2p, *attnp;
    cudaGetSymbolAddress(&nhp, g_nh);
    cudaGetSymbolAddress(&xhp, g_xh);
    cudaGetSymbolAddress(&whp, g_wh);
    cudaGetSymbolAddress(&projp, g_projh);
    cudaGetSymbolAddress(&o1p, g_o1);
    cudaGetSymbolAddress(&o2p, g_o2);
    cudaGetSymbolAddress(&attnp, g_attnh);

    static bool attr_set = false;
    if (!attr_set) {
        cudaFuncSetAttribute(flash_attn_h, cudaFuncAttributeMaxDynamicSharedMemorySize,
                             FA_SMEM_UINTS * 4);
        cudaFuncSetAttribute(hgemm<0>, cudaFuncAttributeMaxDynamicSharedMemorySize, HG_SMEM);
        cudaFuncSetAttribute(hgemm<1>, cudaFuncAttributeMaxDynamicSharedMemorySize, HG_SMEM);
        attr_set = true;
    }

    const dim3 blk(256);
    __half* nh = (__half*)nhp;
    __half* xh = (__half*)xhp;
    __half* wh = (__half*)whp;
    __half* ph = (__half*)projp;

    lambda_kernel<<<1, 64>>>(lq1, lk1, lq2, lk2);

    // fp32 -> fp16 conversion of all operands (q-scale folded into Wq1/Wq2)
    cvt_all<<<dim3(512, 8), blk>>>(noisy, x, Wq1, Wk1, Wq2, Wk2, Wv, Wout, nh, xh, wh);

    // All 5 projections in one batched launch -> head-split fp16 [B,H,T,D]
    hgemm<1><<<dim3(Ec / 128, Mtok / 128, 5), blk, HG_SMEM>>>(
        nh, xh, wh, nullptr, ph, Ec, 1.f);

    // Fused flash attention, one branch per launch
    dim3 gfa(Tc / 128, BHc);
    flash_attn_h<<<gfa, blk, FA_SMEM_UINTS * 4>>>(ph + 0 * SLAB, ph + 1 * SLAB,
                                                  ph + 4 * SLAB, (float*)o1p);
    flash_attn_h<<<gfa, blk, FA_SMEM_UINTS * 4>>>(ph + 2 * SLAB, ph + 3 * SLAB,
                                                  ph + 4 * SLAB, (float*)o2p);

    // Merge + RMSNorm -> fp16 [B,T,E]
    merge_rms<<<BHc * Tc / 8, blk>>>((const float*)o1p, (const float*)o2p, slw, (__half*)attnp);

    // Output projection -> d_out (fp32)
    hgemm<0><<<dim3(Ec / 128, Mtok / 128, 1), blk, HG_SMEM>>>(
        (const __half*)attnp, nullptr, wh + 5 * (size_t)Ec * Ec, out, nullptr, Ec, 1.f);
}

// round 12
// speedup vs baseline: 5.8686x; 1.2724x over previous
#include <cuda_runtime.h>
#include <cuda_fp16.h>
#include <math.h>

// Problem constants
constexpr int Bc   = 2;
constexpr int Tc   = 2048;
constexpr int Ec   = 1024;
constexpr int Hc   = 16;
constexpr int Dc   = 64;
constexpr int BHc  = Bc * Hc;      // 32
constexpr int Mtok = Bc * Tc;      // 4096
constexpr float LAMBDA_INIT = 0.4707130183435843f;  // 0.8 - 0.6*exp(-0.6)
constexpr float EPSc = 1e-5f;
constexpr size_t SLAB = (size_t)BHc * Tc * Dc;      // 4M elems

// Scratch (device globals: allocation-free rule)
__device__ __half g_nh[(size_t)Mtok * Ec];
__device__ __half g_xh[(size_t)Mtok * Ec];
__device__ __half g_wh[6 * (size_t)Ec * Ec];
__device__ __half g_projh[5 * SLAB];          // q1,k1,q2,k2,v
__device__ float  g_o1 [SLAB];
__device__ float  g_o2 [SLAB];
__device__ __half g_attnh[(size_t)Mtok * Ec];
__device__ float  g_lambda;

// -------------------------------------------------------------------------
__device__ __forceinline__ unsigned pack2(float lo, float hi) {
    __half2 h = __floats2half2_rn(lo, hi);
    return *reinterpret_cast<unsigned*>(&h);
}

// fp16 mma m16n8k16, fp32 accumulate
__device__ __forceinline__ void mma_h(float* c, const unsigned* a, const unsigned* b) {
    asm volatile(
        "mma.sync.aligned.m16n8k16.row.col.f32.f16.f16.f32 "
        "{%0,%1,%2,%3}, {%4,%5,%6,%7}, {%8,%9}, {%0,%1,%2,%3};"
        : "+f"(c[0]), "+f"(c[1]), "+f"(c[2]), "+f"(c[3])
        : "r"(a[0]), "r"(a[1]), "r"(a[2]), "r"(a[3]), "r"(b[0]), "r"(b[1]));
}

__device__ __forceinline__ void cp16(unsigned saddr, const void* g) {
    asm volatile("cp.async.cg.shared.global [%0], [%1], 16;\n" :: "r"(saddr), "l"(g));
}
__device__ __forceinline__ void cp_commit() { asm volatile("cp.async.commit_group;\n"); }
template<int N> __device__ __forceinline__ void cp_wait() {
    asm volatile("cp.async.wait_group %0;\n" :: "n"(N));
}
__device__ __forceinline__ void ldmx4(unsigned* r, unsigned addr) {
    asm volatile("ldmatrix.sync.aligned.m8n8.x4.shared.b16 {%0,%1,%2,%3}, [%4];"
        : "=r"(r[0]), "=r"(r[1]), "=r"(r[2]), "=r"(r[3]) : "r"(addr));
}
__device__ __forceinline__ void ldmx4t(unsigned* r, unsigned addr) {
    asm volatile("ldmatrix.sync.aligned.m8n8.x4.trans.shared.b16 {%0,%1,%2,%3}, [%4];"
        : "=r"(r[0]), "=r"(r[1]), "=r"(r[2]), "=r"(r[3]) : "r"(addr));
}

// -------------------------------------------------------------------------
__global__ void lambda_kernel(const float* __restrict__ lq1, const float* __restrict__ lk1,
                              const float* __restrict__ lq2, const float* __restrict__ lk2)
{
    __shared__ float s1[64], s2[64];
    int t = threadIdx.x;
    s1[t] = lq1[t] * lk1[t];
    s2[t] = lq2[t] * lk2[t];
    __syncthreads();
    if (t == 0) {
        float a = 0.f, b = 0.f;
        #pragma unroll
        for (int i = 0; i < 64; i++) { a += s1[i]; b += s2[i]; }
        g_lambda = expf(a) - expf(b) + LAMBDA_INIT;
    }
}

// -------------------------------------------------------------------------
// Convert all fp32 operands to fp16 once. z selects the tensor.
// q-scaling (D^-0.5 = 0.125, exact) folded into Wq1/Wq2.
// -------------------------------------------------------------------------
__global__ __launch_bounds__(256) void cvt_all(
    const float* nsy, const float* xx,
    const float* w0, const float* w1, const float* w2,
    const float* w3, const float* w4, const float* w5,
    __half* nh, __half* xh, __half* wh)
{
    int z = blockIdx.y;
    const float* s; __half* d; int n; float scl = 1.f;
    switch (z) {
        case 0: s = nsy; d = nh; n = Mtok * Ec; break;
        case 1: s = xx;  d = xh; n = Mtok * Ec; break;
        case 2: s = w0; d = wh + 0 * (size_t)Ec * Ec; n = Ec * Ec; scl = 0.125f; break;
        case 3: s = w1; d = wh + 1 * (size_t)Ec * Ec; n = Ec * Ec; break;
        case 4: s = w2; d = wh + 2 * (size_t)Ec * Ec; n = Ec * Ec; scl = 0.125f; break;
        case 5: s = w3; d = wh + 3 * (size_t)Ec * Ec; n = Ec * Ec; break;
        case 6: s = w4; d = wh + 4 * (size_t)Ec * Ec; n = Ec * Ec; break;
        default: s = w5; d = wh + 5 * (size_t)Ec * Ec; n = Ec * Ec; break;
    }
    int n4 = n >> 2;
    for (int i = blockIdx.x * blockDim.x + threadIdx.x; i < n4; i += gridDim.x * blockDim.x) {
        float4 v = ((const float4*)s)[i];
        ((__half2*)d)[2*i]   = __floats2half2_rn(v.x * scl, v.y * scl);
        ((__half2*)d)[2*i+1] = __floats2half2_rn(v.z * scl, v.w * scl);
    }
}

// -------------------------------------------------------------------------
// Pipelined fp16 NT HGEMM (unchanged from R11).
// -------------------------------------------------------------------------
constexpr int TILEB = 128 * 80;
constexpr int HG_SMEM = 3 * 2 * TILEB;

template<int MODE>
__global__ __launch_bounds__(256, 2) void hgemm(
    const __half* __restrict__ Nbase, const __half* __restrict__ Xbase,
    const __half* __restrict__ Wbase, float* __restrict__ Cf,
    __half* __restrict__ Cproj, int K, float scale)
{
    extern __shared__ char dynsm[];
    const unsigned sbase = (unsigned)__cvta_generic_to_shared(dynsm);

    const int z = blockIdx.z;
    const __half* Aop;
    const __half* Wop;
    __half* Cp = nullptr;
    if (MODE == 1) {
        Aop = (z == 2 || z == 3) ? Xbase : Nbase;
        Wop = Wbase + (size_t)z * Ec * Ec;
        Cp  = Cproj + (size_t)z * SLAB;
    } else {
        Aop = Nbase;
        Wop = Wbase;
    }

    const int m0 = blockIdx.y * 128;
    const int n0 = blockIdx.x * 128;
    const int N  = gridDim.x * 128;
    const int tid  = threadIdx.x;
    const int warp = tid >> 5, lane = tid & 31;
    const int g = lane >> 2, tig = lane & 3;
    const int wm = (warp & 1) * 64;
    const int wn = (warp >> 1) * 32;

    auto load_stage = [&](int kt, int s) {
        unsigned sa = sbase + s * (2 * TILEB);
        unsigned sb = sa + TILEB;
        const __half* Ap = Aop + (size_t)m0 * K + kt * 32;
        const __half* Wp = Wop + (size_t)n0 * K + kt * 32;
        #pragma unroll
        for (int j2 = 0; j2 < 2; j2++) {
            int cid = tid + j2 * 256;
            int row = cid >> 2, cc = cid & 3;
            cp16(sa + row * 80 + cc * 16, Ap + (size_t)row * K + cc * 8);
            cp16(sb + row * 80 + cc * 16, Wp + (size_t)row * K + cc * 8);
        }
    };

    float acc[4][4][4];
    #pragma unroll
    for (int i = 0; i < 4; i++)
        #pragma unroll
        for (int j = 0; j < 4; j++)
            #pragma unroll
            for (int r = 0; r < 4; r++) acc[i][j][r] = 0.f;

    const int KT = K / 32;
    load_stage(0, 0); cp_commit();
    load_stage(1, 1); cp_commit();

    for (int kt = 0; kt < KT; kt++) {
        cp_wait<1>();
        __syncthreads();
        if (kt + 2 < KT) load_stage(kt + 2, (kt + 2) % 3);
        cp_commit();

        const int s = kt % 3;
        unsigned aS = sbase + s * (2 * TILEB);
        unsigned bS = aS + TILEB;

        #pragma unroll
        for (int kc = 0; kc < 2; kc++) {
            unsigned a[4][4], b[4][2];
            #pragma unroll
            for (int i = 0; i < 4; i++) {
                int row = wm + i * 16 + ((lane >> 3) & 1) * 8 + (lane & 7);
                int ch  = kc * 2 + (lane >> 4);
                ldmx4(a[i], aS + row * 80 + ch * 16);
            }
            #pragma unroll
            for (int jp = 0; jp < 2; jp++) {
                int mat = lane >> 3;
                int row = wn + jp * 16 + (mat >> 1) * 8 + (lane & 7);
                int ch  = kc * 2 + (mat & 1);
                ldmx4(&b[2 * jp][0], bS + row * 80 + ch * 16);
            }
            #pragma unroll
            for (int i = 0; i < 4; i++)
                #pragma unroll
                for (int j = 0; j < 4; j++)
                    mma_h(acc[i][j], a[i], b[j]);
        }
        __syncthreads();
    }

    if (MODE == 0) {
        #pragma unroll
        for (int i = 0; i < 4; i++) {
            int r0 = m0 + wm + i * 16 + g;
            #pragma unroll
            for (int j = 0; j < 4; j++) {
                int col = n0 + wn + j * 8 + 2 * tig;
                float2 v0 = { acc[i][j][0] * scale, acc[i][j][1] * scale };
                float2 v1 = { acc[i][j][2] * scale, acc[i][j][3] * scale };
                *(float2*)(Cf + (size_t)r0 * N + col)       = v0;
                *(float2*)(Cf + (size_t)(r0 + 8) * N + col) = v1;
            }
        }
    } else {
        #pragma unroll
        for (int i = 0; i < 4; i++)
            #pragma unroll
            for (int rr = 0; rr < 2; rr++) {
                int m  = m0 + wm + i * 16 + g + rr * 8;
                int bb = m >> 11;
                int t  = m & (Tc - 1);
                #pragma unroll
                for (int j = 0; j < 4; j++) {
                    int col = n0 + wn + j * 8 + 2 * tig;
                    int h = col >> 6, d = col & (Dc - 1);
                    __half2 hv = __floats2half2_rn(acc[i][j][rr*2+0], acc[i][j][rr*2+1]);
                    *(__half2*)(Cp + ((size_t)(bb * Hc + h) * Tc + t) * Dc + d) = hv;
                }
            }
    }
}

// -------------------------------------------------------------------------
// Flash attention v2: 256 threads, 8 warps x 32 q-rows (block q-tile 256).
// Q/K/V in natural [row][d] smem layout (144B row stride), cp.async 3-stage
// K/V pipeline, ldmatrix for all fragments (V via .trans).
// -------------------------------------------------------------------------
constexpr int FA_Q_OFF  = 0;                         // 256 rows x 144B
constexpr int FA_KV_OFF = 256 * 144;                 // 36864
constexpr int FA_STAGE  = 2 * 64 * 144;              // K + V per stage: 18432
constexpr int FA_P_OFF  = FA_KV_OFF + 3 * FA_STAGE;  // 92160
constexpr int FA_BYTES  = FA_P_OFF + 8 * 32 * 144;   // 129024

__global__ __launch_bounds__(256) void flash_attn2(
    const __half* __restrict__ Qg, const __half* __restrict__ Kg,
    const __half* __restrict__ Vg, float* __restrict__ Og)
{
    extern __shared__ char fsm[];
    const unsigned sb = (unsigned)__cvta_generic_to_shared(fsm);
    const int bh = blockIdx.y, qt = blockIdx.x;
    const int tid = threadIdx.x, lane = tid & 31, warp = tid >> 5;
    const int g = lane >> 2, tig = lane & 3;
    const int wm = warp * 32;
    const int l15 = lane & 15, l7 = lane & 7;
    const int hi16 = (lane >> 4) << 4;            // 0 or 16 (byte)
    const int hb8  = ((lane >> 3) & 1) << 4;      // 0 or 16 (byte)
    const int hr8  = ((lane >> 4) << 3);          // 0 or 8 (row)
    const int hr8b = ((lane >> 3) & 1) << 3;      // 0 or 8 (row)

    const __half* Qp = Qg + ((size_t)bh * Tc + qt * 256) * Dc;
    const __half* Kp = Kg + (size_t)bh * Tc * Dc;
    const __half* Vp = Vg + (size_t)bh * Tc * Dc;

    // Q: thread t loads row t (8 x 16B)
    {
        const __half* qr = Qp + (size_t)tid * Dc;
        unsigned qd = sb + FA_Q_OFF + tid * 144;
        #pragma unroll
        for (int j = 0; j < 8; j++) cp16(qd + j * 16, qr + j * 8);
    }
    auto load_kv = [&](int kt, int s) {
        unsigned kb = sb + FA_KV_OFF + s * FA_STAGE;
        unsigned vb = kb + 64 * 144;
        const __half* kgp = Kp + (size_t)kt * 64 * Dc;
        const __half* vgp = Vp + (size_t)kt * 64 * Dc;
        #pragma unroll
        for (int l = 0; l < 2; l++) {
            int id = tid + l * 256;
            int row = id >> 3, ch = id & 7;
            cp16(kb + row * 144 + ch * 16, kgp + (size_t)row * Dc + ch * 8);
            cp16(vb + row * 144 + ch * 16, vgp + (size_t)row * Dc + ch * 8);
        }
    };

    load_kv(0, 0); cp_commit();
    load_kv(1, 1); cp_commit();

    float o[2][8][4];
    #pragma unroll
    for (int s2 = 0; s2 < 2; s2++)
        #pragma unroll
        for (int nd = 0; nd < 8; nd++)
            #pragma unroll
            for (int r = 0; r < 4; r++) o[s2][nd][r] = 0.f;
    float mst[2][2] = { {-1e30f, -1e30f}, {-1e30f, -1e30f} };
    float sst[2][2] = { {0.f, 0.f}, {0.f, 0.f} };

    const unsigned Pb = sb + FA_P_OFF + warp * (32 * 144);
    char* Pgen = fsm + FA_P_OFF + warp * (32 * 144);

    const int NKT = Tc / 64;
    for (int kt = 0; kt < NKT; kt++) {
        cp_wait<1>();
        __syncthreads();
        if (kt + 2 < NKT) load_kv(kt + 2, (kt + 2) % 3);
        cp_commit();

        const int s = kt % 3;
        const unsigned Kb = sb + FA_KV_OFF + s * FA_STAGE;
        const unsigned Vb = Kb + 64 * 144;

        // ---- S + online softmax, subtile-sequential (16 rows each) ----
        #pragma unroll
        for (int sub = 0; sub < 2; sub++) {
            float sc[8][4];
            #pragma unroll
            for (int ns = 0; ns < 8; ns++)
                #pragma unroll
                for (int r = 0; r < 4; r++) sc[ns][r] = 0.f;

            #pragma unroll
            for (int c = 0; c < 4; c++) {
                unsigned a[4];
                ldmx4(a, sb + FA_Q_OFF + (wm + sub * 16 + l15) * 144 + 32 * c + hi16);
                #pragma unroll
                for (int np = 0; np < 4; np++) {
                    unsigned bb[4];
                    ldmx4(bb, Kb + (16 * np + l7 + hr8) * 144 + 32 * c + hb8);
                    mma_h(sc[2 * np],     a, bb);
                    mma_h(sc[2 * np + 1], a, bb + 2);
                }
            }

            float mx0 = -1e30f, mx1 = -1e30f;
            #pragma unroll
            for (int ns = 0; ns < 8; ns++) {
                mx0 = fmaxf(mx0, fmaxf(sc[ns][0], sc[ns][1]));
                mx1 = fmaxf(mx1, fmaxf(sc[ns][2], sc[ns][3]));
            }
            mx0 = fmaxf(mx0, __shfl_xor_sync(0xffffffffu, mx0, 1));
            mx0 = fmaxf(mx0, __shfl_xor_sync(0xffffffffu, mx0, 2));
            mx1 = fmaxf(mx1, __shfl_xor_sync(0xffffffffu, mx1, 1));
            mx1 = fmaxf(mx1, __shfl_xor_sync(0xffffffffu, mx1, 2));
            float nm0 = fmaxf(mst[sub][0], mx0), nm1 = fmaxf(mst[sub][1], mx1);
            float cor0 = __expf(mst[sub][0] - nm0), cor1 = __expf(mst[sub][1] - nm1);
            mst[sub][0] = nm0; mst[sub][1] = nm1;

            float sum0 = 0.f, sum1 = 0.f;
            #pragma unroll
            for (int ns = 0; ns < 8; ns++) {
                float p0 = __expf(sc[ns][0] - nm0);
                float p1 = __expf(sc[ns][1] - nm0);
                float p2 = __expf(sc[ns][2] - nm1);
                float p3 = __expf(sc[ns][3] - nm1);
                sum0 += p0 + p1; sum1 += p2 + p3;
                *(unsigned*)(Pgen + (sub * 16 + g)     * 144 + 16 * ns + 4 * tig) = pack2(p0, p1);
                *(unsigned*)(Pgen + (sub * 16 + g + 8) * 144 + 16 * ns + 4 * tig) = pack2(p2, p3);
            }
            sum0 += __shfl_xor_sync(0xffffffffu, sum0, 1);
            sum0 += __shfl_xor_sync(0xffffffffu, sum0, 2);
            sum1 += __shfl_xor_sync(0xffffffffu, sum1, 1);
            sum1 += __shfl_xor_sync(0xffffffffu, sum1, 2);
            sst[sub][0] = sst[sub][0] * cor0 + sum0;
            sst[sub][1] = sst[sub][1] * cor1 + sum1;
            #pragma unroll
            for (int nd = 0; nd < 8; nd++) {
                o[sub][nd][0] *= cor0; o[sub][nd][1] *= cor0;
                o[sub][nd][2] *= cor1; o[sub][nd][3] *= cor1;
            }
        }
        __syncwarp();

        // ---- O += P . V  (V frags shared across both subtiles) ----
        #pragma unroll
        for (int c = 0; c < 4; c++) {
            unsigned aP0[4], aP1[4];
            ldmx4(aP0, Pb + l15 * 144        + 32 * c + hi16);
            ldmx4(aP1, Pb + (16 + l15) * 144 + 32 * c + hi16);
            #pragma unroll
            for (int np = 0; np < 4; np++) {
                unsigned bV[4];
                ldmx4t(bV, Vb + (16 * c + l7 + hr8b) * 144 + 32 * np + hi16);
                mma_h(o[0][2 * np],     aP0, bV);
                mma_h(o[0][2 * np + 1], aP0, bV + 2);
                mma_h(o[1][2 * np],     aP1, bV);
                mma_h(o[1][2 * np + 1], aP1, bV + 2);
            }
        }
        __syncthreads();
    }

    // ---- normalize + write O (fp32, [bh][T][D]) ----
    float* ob = Og + (size_t)bh * Tc * Dc;
    #pragma unroll
    for (int sub = 0; sub < 2; sub++) {
        float inv0 = 1.0f / sst[sub][0], inv1 = 1.0f / sst[sub][1];
        int row0 = qt * 256 + wm + sub * 16 + g;
        #pragma unroll
        for (int nd = 0; nd < 8; nd++) {
            int col = nd * 8 + 2 * tig;
            float2 v0 = { o[sub][nd][0] * inv0, o[sub][nd][1] * inv0 };
            float2 v1 = { o[sub][nd][2] * inv1, o[sub][nd][3] * inv1 };
            *(float2*)(ob + (size_t)row0 * Dc + col)       = v0;
            *(float2*)(ob + (size_t)(row0 + 8) * Dc + col) = v1;
        }
    }
}

// -------------------------------------------------------------------------
// merge O1 - lam*O2, RMSNorm over D, affine, (1-lambda_init), transpose,
// write fp16 for the output projection.  One warp per (bh,t) row.
// -------------------------------------------------------------------------
__global__ __launch_bounds__(256) void merge_rms(
    const float* __restrict__ o1, const float* __restrict__ o2,
    const float* __restrict__ w, __half* __restrict__ O)
{
    int r    = blockIdx.x * 8 + (threadIdx.x >> 5);
    int lane = threadIdx.x & 31;
    float lam = g_lambda;

    const float* p1 = o1 + (size_t)r * Dc;
    const float* p2 = o2 + (size_t)r * Dc;
    float a = p1[lane]      - lam * p2[lane];
    float b = p1[lane + 32] - lam * p2[lane + 32];
    float ss = a * a + b * b;
    #pragma unroll
    for (int o = 16; o; o >>= 1) ss += __shfl_xor_sync(0xffffffffu, ss, o);
    float rr = rsqrtf(ss * (1.0f / Dc) + EPSc) * (1.0f - LAMBDA_INIT);

    int bh = r >> 11, t = r & (Tc - 1);
    int bb = bh >> 4, h = bh & (Hc - 1);
    __half* o = O + ((size_t)(bb * Tc + t)) * Ec + h * Dc;
    o[lane]      = __float2half(a * rr * w[lane]);
    o[lane + 32] = __float2half(b * rr * w[lane + 32]);
}

// -------------------------------------------------------------------------
extern "C" void kernel_launch(void* const* d_in, const int* in_sizes, int n_in,
                              void* d_out, int out_size)
{
    const float* noisy = (const float*)d_in[0];
    const float* x     = (const float*)d_in[1];
    const float* Wq1   = (const float*)d_in[2];
    const float* Wk1   = (const float*)d_in[3];
    const float* Wq2   = (const float*)d_in[4];
    const float* Wk2   = (const float*)d_in[5];
    const float* Wv    = (const float*)d_in[6];
    const float* Wout  = (const float*)d_in[7];
    const float* lq1   = (const float*)d_in[8];
    const float* lk1   = (const float*)d_in[9];
    const float* lq2   = (const float*)d_in[10];
    const float* lk2   = (const float*)d_in[11];
    const float* slw   = (const float*)d_in[12];
    float* out = (float*)d_out;

    void *nhp, *xhp, *whp, *projp, *o1p, *o2p, *attnp;
    cudaGetSymbolAddress(&nhp, g_nh);
    cudaGetSymbolAddress(&xhp, g_xh);
    cudaGetSymbolAddress(&whp, g_wh);
    cudaGetSymbolAddress(&projp, g_projh);
    cudaGetSymbolAddress(&o1p, g_o1);
    cudaGetSymbolAddress(&o2p, g_o2);
    cudaGetSymbolAddress(&attnp, g_attnh);

    static bool attr_set = false;
    if (!attr_set) {
        cudaFuncSetAttribute(flash_attn2, cudaFuncAttributeMaxDynamicSharedMemorySize, FA_BYTES);
        cudaFuncSetAttribute(hgemm<0>, cudaFuncAttributeMaxDynamicSharedMemorySize, HG_SMEM);
        cudaFuncSetAttribute(hgemm<1>, cudaFuncAttributeMaxDynamicSharedMemorySize, HG_SMEM);
        attr_set = true;
    }

    const dim3 blk(256);
    __half* nh = (__half*)nhp;
    __half* xh = (__half*)xhp;
    __half* wh = (__half*)whp;
    __half* ph = (__half*)projp;

    lambda_kernel<<<1, 64>>>(lq1, lk1, lq2, lk2);

    // fp32 -> fp16 conversion of all operands (q-scale folded into Wq1/Wq2)
    cvt_all<<<dim3(512, 8), blk>>>(noisy, x, Wq1, Wk1, Wq2, Wk2, Wv, Wout, nh, xh, wh);

    // All 5 projections in one batched launch -> head-split fp16 [B,H,T,D]
    hgemm<1><<<dim3(Ec / 128, Mtok / 128, 5), blk, HG_SMEM>>>(
        nh, xh, wh, nullptr, ph, Ec, 1.f);

    // Fused flash attention, one branch per launch
    dim3 gfa(Tc / 256, BHc);
    flash_attn2<<<gfa, blk, FA_BYTES>>>(ph + 0 * SLAB, ph + 1 * SLAB,
                                        ph + 4 * SLAB, (float*)o1p);
    flash_attn2<<<gfa, blk, FA_BYTES>>>(ph + 2 * SLAB, ph + 3 * SLAB,
                                        ph + 4 * SLAB, (float*)o2p);

    // Merge + RMSNorm -> fp16 [B,T,E]
    merge_rms<<<BHc * Tc / 8, blk>>>((const float*)o1p, (const float*)o2p, slw, (__half*)attnp);

    // Output projection -> d_out (fp32)
    hgemm<0><<<dim3(Ec / 128, Mtok / 128, 1), blk, HG_SMEM>>>(
        (const __half*)attnp, nullptr, wh + 5 * (size_t)Ec * Ec, out, nullptr, Ec, 1.f);
}